// round 2
// baseline (speedup 1.0000x reference)
#include <cuda_runtime.h>
#include <math.h>

// Problem constants
#define T_TOK 4096
#define D_DIM 512
#define F_DIM 2048
#define E_EXP 8
#define NS_SH 2
#define TOPK 2

// GEMM tiling
#define BM 64
#define BN 64
#define BK 16

#define ROWS_CAP (2*T_TOK + E_EXP*BM)   // 8704 padded routed rows

// ---- device scratch (allocation-free rule: __device__ globals) ----
__device__ float g_Hs[NS_SH * T_TOK * F_DIM];   // shared FFN hidden  (64 MB)
__device__ float g_Hr[ROWS_CAP * F_DIM];        // routed FFN hidden  (71 MB)
__device__ float g_Or[ROWS_CAP * D_DIM];        // routed FFN output  (18 MB)
__device__ int   g_counts[E_EXP];
__device__ int   g_poff[E_EXP + 1];
__device__ int   g_cursor[E_EXP];
__device__ int   g_ntiles[E_EXP];
__device__ int   g_eid[T_TOK * TOPK];
__device__ float g_wt[T_TOK * TOPK];
__device__ int   g_rows[T_TOK * TOPK];
__device__ int   g_row_token[ROWS_CAP];

__device__ __forceinline__ float gelu_exact(float v) {
    return 0.5f * v * (1.0f + erff(v * 0.70710678118654752440f));
}

// ---- K0: reset per-call state ----
__global__ void k_init() {
    int i = blockIdx.x * blockDim.x + threadIdx.x;
    if (i < E_EXP) g_counts[i] = 0;
    if (i < ROWS_CAP) g_row_token[i] = 0;
}

// ---- K1: router (one warp per token): logits, softmax, top-2, counts ----
__global__ void k_router(const float* __restrict__ x,
                         const float* __restrict__ gw,
                         const float* __restrict__ gb) {
    int warp = (blockIdx.x * blockDim.x + threadIdx.x) >> 5;
    int lane = threadIdx.x & 31;
    if (warp >= T_TOK) return;
    const float* xr = x + warp * D_DIM;
    float xv[16];
#pragma unroll
    for (int i = 0; i < 16; i++) xv[i] = xr[lane + 32 * i];
    float acc[E_EXP];
#pragma unroll
    for (int e = 0; e < E_EXP; e++) acc[e] = 0.f;
#pragma unroll
    for (int i = 0; i < 16; i++) {
        int d = lane + 32 * i;
#pragma unroll
        for (int e = 0; e < E_EXP; e++) acc[e] += xv[i] * gw[e * D_DIM + d];
    }
#pragma unroll
    for (int e = 0; e < E_EXP; e++) {
#pragma unroll
        for (int off = 16; off; off >>= 1)
            acc[e] += __shfl_xor_sync(0xffffffffu, acc[e], off);
    }
    if (lane == 0) {
        float lg[E_EXP], mx = -1e30f;
#pragma unroll
        for (int e = 0; e < E_EXP; e++) { lg[e] = acc[e] + gb[e]; mx = fmaxf(mx, lg[e]); }
        float s = 0.f;
#pragma unroll
        for (int e = 0; e < E_EXP; e++) { lg[e] = expf(lg[e] - mx); s += lg[e]; }
        float inv = 1.f / s;
#pragma unroll
        for (int e = 0; e < E_EXP; e++) lg[e] *= inv;
        int i1 = 0; float v1 = -1.f;
#pragma unroll
        for (int e = 0; e < E_EXP; e++) { if (lg[e] > v1) { v1 = lg[e]; i1 = e; } }
        int i2 = -1; float v2 = -1.f;
#pragma unroll
        for (int e = 0; e < E_EXP; e++) { if (e != i1 && lg[e] > v2) { v2 = lg[e]; i2 = e; } }
        g_eid[warp * 2 + 0] = i1;  g_wt[warp * 2 + 0] = v1;
        g_eid[warp * 2 + 1] = i2;  g_wt[warp * 2 + 1] = v2;
        atomicAdd(&g_counts[i1], 1);
        atomicAdd(&g_counts[i2], 1);
    }
}

// ---- K2: tiny scan (E=8) -> padded segment offsets / tile counts ----
__global__ void k_scan() {
    int off = 0;
    for (int e = 0; e < E_EXP; e++) {
        g_poff[e] = off;
        g_cursor[e] = off;
        int nt = (g_counts[e] + BM - 1) / BM;
        g_ntiles[e] = nt;
        off += nt * BM;
    }
    g_poff[E_EXP] = off;
}

// ---- K3: assign tokens to rows inside padded expert segments ----
__global__ void k_assign() {
    int t = blockIdx.x * blockDim.x + threadIdx.x;
    if (t >= T_TOK) return;
#pragma unroll
    for (int k = 0; k < TOPK; k++) {
        int e = g_eid[t * 2 + k];
        int r = atomicAdd(&g_cursor[e], 1);
        g_rows[t * 2 + k] = r;
        g_row_token[r] = t;
    }
}

// ---- FFN layer 1 (shared or routed): H = gelu(X * W1^T + b1) ----
// C[M,N] = A[M,K(=D)] * B[N,K]^T, NT GEMM, 64x64x16 tiles, 256 threads, 4x4 micro.
template<bool ROUTED>
__global__ void k_ffn1(const float* __restrict__ x,
                       const float* __restrict__ w1,
                       const float* __restrict__ b1) {
    int z = blockIdx.z;
    int row0;
    const float* w;
    const float* bias;
    float* H;
    if (ROUTED) {
        if ((int)blockIdx.y >= g_ntiles[z]) return;
        row0 = g_poff[z] + blockIdx.y * BM;
        w = w1 + z * F_DIM * D_DIM;
        bias = b1 + z * F_DIM;
        H = g_Hr;
    } else {
        row0 = blockIdx.y * BM;
        w = w1 + z * F_DIM * D_DIM;
        bias = b1 + z * F_DIM;
        H = g_Hs + z * (T_TOK * F_DIM);
    }
    int col0 = blockIdx.x * BN;

    __shared__ float As[BK][BM];
    __shared__ float Bs[BK][BN];
    int tid = threadIdx.x;
    int lr = tid >> 2;
    int lk = (tid & 3) * 4;
    int ty = tid >> 4, tx = tid & 15;

    int arow = row0 + lr;
    int tok = ROUTED ? g_row_token[arow] : arow;
    const float* aptr = x + tok * D_DIM + lk;
    const float* bptr = w + (col0 + lr) * D_DIM + lk;

    float acc[4][4] = {};
    for (int k0 = 0; k0 < D_DIM; k0 += BK) {
        float4 av = *(const float4*)(aptr + k0);
        float4 bv = *(const float4*)(bptr + k0);
        As[lk + 0][lr] = av.x; As[lk + 1][lr] = av.y; As[lk + 2][lr] = av.z; As[lk + 3][lr] = av.w;
        Bs[lk + 0][lr] = bv.x; Bs[lk + 1][lr] = bv.y; Bs[lk + 2][lr] = bv.z; Bs[lk + 3][lr] = bv.w;
        __syncthreads();
#pragma unroll
        for (int kk = 0; kk < BK; kk++) {
            float a[4], b[4];
#pragma unroll
            for (int i = 0; i < 4; i++) a[i] = As[kk][ty * 4 + i];
#pragma unroll
            for (int j = 0; j < 4; j++) b[j] = Bs[kk][tx * 4 + j];
#pragma unroll
            for (int i = 0; i < 4; i++)
#pragma unroll
                for (int j = 0; j < 4; j++) acc[i][j] += a[i] * b[j];
        }
        __syncthreads();
    }
#pragma unroll
    for (int i = 0; i < 4; i++) {
        int r = row0 + ty * 4 + i;
        float* outp = H + r * F_DIM + col0;
#pragma unroll
        for (int j = 0; j < 4; j++) {
            int c = tx * 4 + j;
            outp[c] = gelu_exact(acc[i][j] + bias[col0 + c]);
        }
    }
}

// ---- shared FFN layer 2 over K = NS*F: out[t,d] = sum_{n,f} Hs*sw2 + sum_n sb2 ----
__global__ void k_ffn2_shared(const float* __restrict__ sw2,
                              const float* __restrict__ sb2,
                              float* __restrict__ out) {
    int row0 = blockIdx.y * BM;
    int col0 = blockIdx.x * BN;
    __shared__ float As[BK][BM];
    __shared__ float Bs[BK][BN];
    int tid = threadIdx.x;
    int lr = tid >> 2;
    int lk = (tid & 3) * 4;
    int ty = tid >> 4, tx = tid & 15;
    float acc[4][4] = {};
    for (int k0 = 0; k0 < NS_SH * F_DIM; k0 += BK) {
        int n = k0 >> 11;            // /F_DIM
        int f = k0 & (F_DIM - 1);
        float4 av = *(const float4*)(g_Hs + n * (T_TOK * F_DIM) + (row0 + lr) * F_DIM + f + lk);
        float4 bv = *(const float4*)(sw2 + n * (D_DIM * F_DIM) + (col0 + lr) * F_DIM + f + lk);
        As[lk + 0][lr] = av.x; As[lk + 1][lr] = av.y; As[lk + 2][lr] = av.z; As[lk + 3][lr] = av.w;
        Bs[lk + 0][lr] = bv.x; Bs[lk + 1][lr] = bv.y; Bs[lk + 2][lr] = bv.z; Bs[lk + 3][lr] = bv.w;
        __syncthreads();
#pragma unroll
        for (int kk = 0; kk < BK; kk++) {
            float a[4], b[4];
#pragma unroll
            for (int i = 0; i < 4; i++) a[i] = As[kk][ty * 4 + i];
#pragma unroll
            for (int j = 0; j < 4; j++) b[j] = Bs[kk][tx * 4 + j];
#pragma unroll
            for (int i = 0; i < 4; i++)
#pragma unroll
                for (int j = 0; j < 4; j++) acc[i][j] += a[i] * b[j];
        }
        __syncthreads();
    }
#pragma unroll
    for (int i = 0; i < 4; i++) {
        int r = row0 + ty * 4 + i;
#pragma unroll
        for (int j = 0; j < 4; j++) {
            int c = col0 + tx * 4 + j;
            out[r * D_DIM + c] = acc[i][j] + sb2[c] + sb2[D_DIM + c];
        }
    }
}

// ---- routed FFN layer 2: Or[r,d] = Hr[r,:] . rw2[e,d,:] + rb2[e,d] ----
__global__ void k_ffn2_routed(const float* __restrict__ rw2,
                              const float* __restrict__ rb2) {
    int e = blockIdx.z;
    if ((int)blockIdx.y >= g_ntiles[e]) return;
    int row0 = g_poff[e] + blockIdx.y * BM;
    int col0 = blockIdx.x * BN;
    __shared__ float As[BK][BM];
    __shared__ float Bs[BK][BN];
    int tid = threadIdx.x;
    int lr = tid >> 2;
    int lk = (tid & 3) * 4;
    int ty = tid >> 4, tx = tid & 15;
    const float* aptr = g_Hr + (row0 + lr) * F_DIM + lk;
    const float* bptr = rw2 + e * (D_DIM * F_DIM) + (col0 + lr) * F_DIM + lk;
    float acc[4][4] = {};
    for (int k0 = 0; k0 < F_DIM; k0 += BK) {
        float4 av = *(const float4*)(aptr + k0);
        float4 bv = *(const float4*)(bptr + k0);
        As[lk + 0][lr] = av.x; As[lk + 1][lr] = av.y; As[lk + 2][lr] = av.z; As[lk + 3][lr] = av.w;
        Bs[lk + 0][lr] = bv.x; Bs[lk + 1][lr] = bv.y; Bs[lk + 2][lr] = bv.z; Bs[lk + 3][lr] = bv.w;
        __syncthreads();
#pragma unroll
        for (int kk = 0; kk < BK; kk++) {
            float a[4], b[4];
#pragma unroll
            for (int i = 0; i < 4; i++) a[i] = As[kk][ty * 4 + i];
#pragma unroll
            for (int j = 0; j < 4; j++) b[j] = Bs[kk][tx * 4 + j];
#pragma unroll
            for (int i = 0; i < 4; i++)
#pragma unroll
                for (int j = 0; j < 4; j++) acc[i][j] += a[i] * b[j];
        }
        __syncthreads();
    }
#pragma unroll
    for (int i = 0; i < 4; i++) {
        int r = row0 + ty * 4 + i;
#pragma unroll
        for (int j = 0; j < 4; j++) {
            int c = col0 + tx * 4 + j;
            g_Or[r * D_DIM + c] = acc[i][j] + rb2[e * D_DIM + c];
        }
    }
}

// ---- K8: combine routed contributions into out (per-token gather, no atomics) ----
__global__ void k_combine(float* __restrict__ out) {
    int idx = blockIdx.x * blockDim.x + threadIdx.x;
    if (idx >= T_TOK * (D_DIM / 4)) return;
    int t = idx >> 7;            // D/4 = 128
    int dq = idx & 127;
    float4 o = ((float4*)out)[t * 128 + dq];
    int r0 = g_rows[t * 2 + 0], r1 = g_rows[t * 2 + 1];
    float w0 = g_wt[t * 2 + 0], w1 = g_wt[t * 2 + 1];
    float4 a = ((const float4*)g_Or)[r0 * 128 + dq];
    float4 b = ((const float4*)g_Or)[r1 * 128 + dq];
    o.x += w0 * a.x + w1 * b.x;
    o.y += w0 * a.y + w1 * b.y;
    o.z += w0 * a.z + w1 * b.z;
    o.w += w0 * a.w + w1 * b.w;
    ((float4*)out)[t * 128 + dq] = o;
}

extern "C" void kernel_launch(void* const* d_in, const int* in_sizes, int n_in,
                              void* d_out, int out_size) {
    const float* x   = (const float*)d_in[0];
    const float* gw  = (const float*)d_in[1];
    const float* gb  = (const float*)d_in[2];
    const float* sw1 = (const float*)d_in[3];
    const float* sb1 = (const float*)d_in[4];
    const float* sw2 = (const float*)d_in[5];
    const float* sb2 = (const float*)d_in[6];
    const float* rw1 = (const float*)d_in[7];
    const float* rb1 = (const float*)d_in[8];
    const float* rw2 = (const float*)d_in[9];
    const float* rb2 = (const float*)d_in[10];
    float* out = (float*)d_out;

    k_init<<<(ROWS_CAP + 255) / 256, 256>>>();
    k_router<<<T_TOK / 8, 256>>>(x, gw, gb);
    k_scan<<<1, 1>>>();
    k_assign<<<(T_TOK + 255) / 256, 256>>>();

    dim3 blk(256);
    // shared FFN1: M=T, N=F, K=D, z = NS
    k_ffn1<false><<<dim3(F_DIM / BN, T_TOK / BM, NS_SH), blk>>>(x, sw1, sb1);
    // routed FFN1: padded rows per expert, N=F, K=D, z = E
    k_ffn1<true><<<dim3(F_DIM / BN, T_TOK / BM, E_EXP), blk>>>(x, rw1, rb1);
    // shared FFN2: M=T, N=D, K=NS*F
    k_ffn2_shared<<<dim3(D_DIM / BN, T_TOK / BM), blk>>>(sw2, sb2, out);
    // routed FFN2: padded rows, N=D, K=F
    k_ffn2_routed<<<dim3(D_DIM / BN, T_TOK / BM, E_EXP), blk>>>(rw2, rb2);
    // combine
    k_combine<<<(T_TOK * (D_DIM / 4) + 255) / 256, 256>>>(out);
}

// round 5
// speedup vs baseline: 3.6961x; 3.6961x over previous
#include <cuda_runtime.h>
#include <cuda_bf16.h>
#include <math.h>

// Problem constants
#define T_TOK 4096
#define D_DIM 512
#define F_DIM 2048
#define E_EXP 8
#define NS_SH 2
#define TOPK 2

// GEMM tiling
#define BM 128
#define BN 128
#define BK 32
#define SST 48                       // smem row stride (bf16 elems), 96B: 16B-aligned, conflict-reducing

#define ROWS_CAP (2*T_TOK + E_EXP*BM)   // 9216 padded routed rows

// ---- device scratch (allocation-free rule: __device__ globals) ----
// bf16 hi/lo planes of inputs/weights
__device__ __nv_bfloat16 g_xh [T_TOK*D_DIM],        g_xl [T_TOK*D_DIM];
__device__ __nv_bfloat16 g_w1sh[NS_SH*F_DIM*D_DIM], g_w1sl[NS_SH*F_DIM*D_DIM];
__device__ __nv_bfloat16 g_w2sh[NS_SH*D_DIM*F_DIM], g_w2sl[NS_SH*D_DIM*F_DIM];
__device__ __nv_bfloat16 g_w1rh[E_EXP*F_DIM*D_DIM], g_w1rl[E_EXP*F_DIM*D_DIM];
__device__ __nv_bfloat16 g_w2rh[E_EXP*D_DIM*F_DIM], g_w2rl[E_EXP*D_DIM*F_DIM];
// activations
__device__ __nv_bfloat16 g_Hsh[NS_SH*T_TOK*F_DIM],  g_Hsl[NS_SH*T_TOK*F_DIM];
__device__ __nv_bfloat16 g_Hrh[ROWS_CAP*F_DIM],     g_Hrl[ROWS_CAP*F_DIM];
__device__ float g_Or[ROWS_CAP*D_DIM];
// routing state
__device__ int   g_counts[E_EXP];
__device__ int   g_poff[E_EXP + 1];
__device__ int   g_cursor[E_EXP];
__device__ int   g_ntiles[E_EXP];
__device__ int   g_eid[T_TOK * TOPK];
__device__ float g_wt[T_TOK * TOPK];
__device__ int   g_rows[T_TOK * TOPK];
__device__ int   g_row_token[ROWS_CAP];

__device__ __forceinline__ float gelu_exact(float v) {
    return 0.5f * v * (1.0f + erff(v * 0.70710678118654752440f));
}

// ---- K0: reset per-call state ----
__global__ void k_init() {
    int i = blockIdx.x * blockDim.x + threadIdx.x;
    if (i < E_EXP) g_counts[i] = 0;
    if (i < ROWS_CAP) g_row_token[i] = 0;
}

// ---- fp32 -> bf16 hi/lo split conversion (vectorized x4) ----
__global__ void k_cvt(const float4* __restrict__ s,
                      __nv_bfloat162* __restrict__ h,
                      __nv_bfloat162* __restrict__ l, int n4) {
    int i = blockIdx.x * blockDim.x + threadIdx.x;
    if (i >= n4) return;
    float4 v = s[i];
    __nv_bfloat16 h0 = __float2bfloat16(v.x), h1 = __float2bfloat16(v.y);
    __nv_bfloat16 h2 = __float2bfloat16(v.z), h3 = __float2bfloat16(v.w);
    __nv_bfloat162 p;
    p.x = h0; p.y = h1; h[2*i] = p;
    p.x = h2; p.y = h3; h[2*i+1] = p;
    p.x = __float2bfloat16(v.x - __bfloat162float(h0));
    p.y = __float2bfloat16(v.y - __bfloat162float(h1));
    l[2*i] = p;
    p.x = __float2bfloat16(v.z - __bfloat162float(h2));
    p.y = __float2bfloat16(v.w - __bfloat162float(h3));
    l[2*i+1] = p;
}

// ---- K1: router (one warp per token) ----
__global__ void k_router(const float* __restrict__ x,
                         const float* __restrict__ gw,
                         const float* __restrict__ gb) {
    int warp = (blockIdx.x * blockDim.x + threadIdx.x) >> 5;
    int lane = threadIdx.x & 31;
    if (warp >= T_TOK) return;
    const float* xr = x + warp * D_DIM;
    float xv[16];
#pragma unroll
    for (int i = 0; i < 16; i++) xv[i] = xr[lane + 32 * i];
    float acc[E_EXP];
#pragma unroll
    for (int e = 0; e < E_EXP; e++) acc[e] = 0.f;
#pragma unroll
    for (int i = 0; i < 16; i++) {
        int d = lane + 32 * i;
#pragma unroll
        for (int e = 0; e < E_EXP; e++) acc[e] += xv[i] * gw[e * D_DIM + d];
    }
#pragma unroll
    for (int e = 0; e < E_EXP; e++) {
#pragma unroll
        for (int off = 16; off; off >>= 1)
            acc[e] += __shfl_xor_sync(0xffffffffu, acc[e], off);
    }
    if (lane == 0) {
        float lg[E_EXP], mx = -1e30f;
#pragma unroll
        for (int e = 0; e < E_EXP; e++) { lg[e] = acc[e] + gb[e]; mx = fmaxf(mx, lg[e]); }
        float s = 0.f;
#pragma unroll
        for (int e = 0; e < E_EXP; e++) { lg[e] = expf(lg[e] - mx); s += lg[e]; }
        float inv = 1.f / s;
#pragma unroll
        for (int e = 0; e < E_EXP; e++) lg[e] *= inv;
        int i1 = 0; float v1 = -1.f;
#pragma unroll
        for (int e = 0; e < E_EXP; e++) { if (lg[e] > v1) { v1 = lg[e]; i1 = e; } }
        int i2 = -1; float v2 = -1.f;
#pragma unroll
        for (int e = 0; e < E_EXP; e++) { if (e != i1 && lg[e] > v2) { v2 = lg[e]; i2 = e; } }
        g_eid[warp * 2 + 0] = i1;  g_wt[warp * 2 + 0] = v1;
        g_eid[warp * 2 + 1] = i2;  g_wt[warp * 2 + 1] = v2;
        atomicAdd(&g_counts[i1], 1);
        atomicAdd(&g_counts[i2], 1);
    }
}

// ---- K2: tiny scan -> padded segments (pad to BM=128) ----
__global__ void k_scan() {
    int off = 0;
    for (int e = 0; e < E_EXP; e++) {
        g_poff[e] = off;
        g_cursor[e] = off;
        int nt = (g_counts[e] + BM - 1) / BM;
        g_ntiles[e] = nt;
        off += nt * BM;
    }
    g_poff[E_EXP] = off;
}

// ---- K3: assign tokens to rows inside padded expert segments ----
__global__ void k_assign() {
    int t = blockIdx.x * blockDim.x + threadIdx.x;
    if (t >= T_TOK) return;
#pragma unroll
    for (int k = 0; k < TOPK; k++) {
        int e = g_eid[t * 2 + k];
        int r = atomicAdd(&g_cursor[e], 1);
        g_rows[t * 2 + k] = r;
        g_row_token[r] = t;
    }
}

// ==================== tensor-core GEMM (bf16 hi/lo 3-mma split) ====================
// C[M,N] = A[M,K] * B[N,K]^T  (both K-contiguous), fp32 accumulate.
enum { MF1S = 0, MF1R = 1, MF2S = 2, MF2R = 3 };

__device__ __forceinline__ void mma16816(float& c0, float& c1, float& c2, float& c3,
                                         unsigned a0, unsigned a1, unsigned a2, unsigned a3,
                                         unsigned b0, unsigned b1) {
    asm volatile(
        "mma.sync.aligned.m16n8k16.row.col.f32.bf16.bf16.f32 "
        "{%0,%1,%2,%3},{%4,%5,%6,%7},{%8,%9},{%0,%1,%2,%3};\n"
        : "+f"(c0), "+f"(c1), "+f"(c2), "+f"(c3)
        : "r"(a0), "r"(a1), "r"(a2), "r"(a3), "r"(b0), "r"(b1));
}

__device__ __forceinline__ void st_hilo(__nv_bfloat16* Hh, __nv_bfloat16* Hl,
                                        size_t off, float v0, float v1) {
    __nv_bfloat16 h0 = __float2bfloat16(v0), h1 = __float2bfloat16(v1);
    __nv_bfloat162 p;
    p.x = h0; p.y = h1;
    *(__nv_bfloat162*)(Hh + off) = p;
    p.x = __float2bfloat16(v0 - __bfloat162float(h0));
    p.y = __float2bfloat16(v1 - __bfloat162float(h1));
    *(__nv_bfloat162*)(Hl + off) = p;
}

template<int MODE>
__global__ void __launch_bounds__(256, 1) k_gemm(
    const __nv_bfloat16* __restrict__ Ah, const __nv_bfloat16* __restrict__ Al,
    const __nv_bfloat16* __restrict__ Bh, const __nv_bfloat16* __restrict__ Bl,
    const float* __restrict__ bias, float* __restrict__ outF) {
    int z = blockIdx.z;
    int row0;
    if (MODE == MF1R || MODE == MF2R) {
        if ((int)blockIdx.y >= g_ntiles[z]) return;
        row0 = g_poff[z] + blockIdx.y * BM;
    } else {
        row0 = blockIdx.y * BM;
    }
    int col0 = blockIdx.x * BN;

    const int KA = (MODE == MF1S || MODE == MF1R) ? D_DIM : F_DIM;  // row stride for A and B
    const int KTOT = (MODE == MF2S) ? NS_SH * F_DIM : KA;

    const __nv_bfloat16 *Ah0 = Ah, *Al0 = Al, *Bh0 = Bh, *Bl0 = Bl;
    if (MODE == MF1S || MODE == MF1R) {
        Bh0 += (size_t)z * F_DIM * D_DIM; Bl0 += (size_t)z * F_DIM * D_DIM;
    }
    if (MODE == MF2R) {
        Bh0 += (size_t)z * D_DIM * F_DIM; Bl0 += (size_t)z * D_DIM * F_DIM;
    }

    __shared__ __align__(16) __nv_bfloat16 sAh[BM * SST], sAl[BM * SST];
    __shared__ __align__(16) __nv_bfloat16 sBh[BN * SST], sBl[BN * SST];

    int t = threadIdx.x;
    int lr = t >> 2;          // 0..63: tile row handled by this thread (and +64)
    int ac = (t & 3) * 8;     // element col offset within BK for 16B loads

    int ga0, ga1;  // global A rows
    if (MODE == MF1R) { ga0 = g_row_token[row0 + lr]; ga1 = g_row_token[row0 + lr + 64]; }
    else             { ga0 = row0 + lr;               ga1 = row0 + lr + 64; }
    int gb0 = col0 + lr, gb1 = col0 + lr + 64;

    uint4 rAh0, rAh1, rAl0, rAl1, rBh0, rBh1, rBl0, rBl1;

    auto ld = [&](int k0) {
        const __nv_bfloat16 *pAh = Ah0, *pAl = Al0, *pBh = Bh0, *pBl = Bl0;
        int kk = k0;
        if (MODE == MF2S) {                          // K concat over NS planes
            int pl = k0 >> 11; kk = k0 & (F_DIM - 1);
            size_t ao = (size_t)pl * T_TOK * F_DIM, bo = (size_t)pl * D_DIM * F_DIM;
            pAh += ao; pAl += ao; pBh += bo; pBl += bo;
        }
        rAh0 = *(const uint4*)(pAh + (size_t)ga0 * KA + kk + ac);
        rAh1 = *(const uint4*)(pAh + (size_t)ga1 * KA + kk + ac);
        rAl0 = *(const uint4*)(pAl + (size_t)ga0 * KA + kk + ac);
        rAl1 = *(const uint4*)(pAl + (size_t)ga1 * KA + kk + ac);
        rBh0 = *(const uint4*)(pBh + (size_t)gb0 * KA + kk + ac);
        rBh1 = *(const uint4*)(pBh + (size_t)gb1 * KA + kk + ac);
        rBl0 = *(const uint4*)(pBl + (size_t)gb0 * KA + kk + ac);
        rBl1 = *(const uint4*)(pBl + (size_t)gb1 * KA + kk + ac);
    };

    int wid = t >> 5, lane = t & 31;
    int wr = (wid >> 2) * 64, wc = (wid & 3) * 32;   // 2x4 warp grid, 64x32 warp tile
    int grp = lane >> 2, qp = lane & 3;

    float c[4][4][4];
#pragma unroll
    for (int i = 0; i < 4; i++)
#pragma unroll
        for (int j = 0; j < 4; j++)
#pragma unroll
            for (int q = 0; q < 4; q++) c[i][j][q] = 0.f;

    ld(0);
    int nIter = KTOT / BK;
    for (int it = 0; it < nIter; ++it) {
        *(uint4*)&sAh[lr * SST + ac] = rAh0;  *(uint4*)&sAh[(lr + 64) * SST + ac] = rAh1;
        *(uint4*)&sAl[lr * SST + ac] = rAl0;  *(uint4*)&sAl[(lr + 64) * SST + ac] = rAl1;
        *(uint4*)&sBh[lr * SST + ac] = rBh0;  *(uint4*)&sBh[(lr + 64) * SST + ac] = rBh1;
        *(uint4*)&sBl[lr * SST + ac] = rBl0;  *(uint4*)&sBl[(lr + 64) * SST + ac] = rBl1;
        __syncthreads();
        if (it + 1 < nIter) ld((it + 1) * BK);
#pragma unroll
        for (int ks = 0; ks < 2; ++ks) {
            int kk = ks * 16 + qp * 2;
            unsigned Ahf[4][4], Alf[4][4], Bhf[4][2], Blf[4][2];
#pragma unroll
            for (int mt = 0; mt < 4; ++mt) {
                int o = (wr + mt * 16 + grp) * SST + kk;
                Ahf[mt][0] = *(const unsigned*)&sAh[o];
                Ahf[mt][1] = *(const unsigned*)&sAh[o + 8 * SST];
                Ahf[mt][2] = *(const unsigned*)&sAh[o + 8];
                Ahf[mt][3] = *(const unsigned*)&sAh[o + 8 * SST + 8];
                Alf[mt][0] = *(const unsigned*)&sAl[o];
                Alf[mt][1] = *(const unsigned*)&sAl[o + 8 * SST];
                Alf[mt][2] = *(const unsigned*)&sAl[o + 8];
                Alf[mt][3] = *(const unsigned*)&sAl[o + 8 * SST + 8];
            }
#pragma unroll
            for (int nt = 0; nt < 4; ++nt) {
                int o = (wc + nt * 8 + grp) * SST + kk;
                Bhf[nt][0] = *(const unsigned*)&sBh[o];
                Bhf[nt][1] = *(const unsigned*)&sBh[o + 8];
                Blf[nt][0] = *(const unsigned*)&sBl[o];
                Blf[nt][1] = *(const unsigned*)&sBl[o + 8];
            }
#pragma unroll
            for (int mt = 0; mt < 4; ++mt)
#pragma unroll
                for (int nt = 0; nt < 4; ++nt) {
                    mma16816(c[mt][nt][0], c[mt][nt][1], c[mt][nt][2], c[mt][nt][3],
                             Ahf[mt][0], Ahf[mt][1], Ahf[mt][2], Ahf[mt][3],
                             Bhf[nt][0], Bhf[nt][1]);
                    mma16816(c[mt][nt][0], c[mt][nt][1], c[mt][nt][2], c[mt][nt][3],
                             Ahf[mt][0], Ahf[mt][1], Ahf[mt][2], Ahf[mt][3],
                             Blf[nt][0], Blf[nt][1]);
                    mma16816(c[mt][nt][0], c[mt][nt][1], c[mt][nt][2], c[mt][nt][3],
                             Alf[mt][0], Alf[mt][1], Alf[mt][2], Alf[mt][3],
                             Bhf[nt][0], Bhf[nt][1]);
                }
        }
        __syncthreads();
    }

    // epilogue
#pragma unroll
    for (int mt = 0; mt < 4; ++mt) {
        int r = row0 + wr + mt * 16 + grp;
#pragma unroll
        for (int nt = 0; nt < 4; ++nt) {
            int cg = col0 + wc + nt * 8 + qp * 2;
            float c0 = c[mt][nt][0], c1 = c[mt][nt][1];
            float c2 = c[mt][nt][2], c3 = c[mt][nt][3];
            if (MODE == MF1S || MODE == MF1R) {
                float b0 = bias[z * F_DIM + cg], b1 = bias[z * F_DIM + cg + 1];
                float h0 = gelu_exact(c0 + b0), h1 = gelu_exact(c1 + b1);
                float h2 = gelu_exact(c2 + b0), h3 = gelu_exact(c3 + b1);
                __nv_bfloat16 *Hh, *Hl;
                if (MODE == MF1S) {
                    Hh = g_Hsh + (size_t)z * T_TOK * F_DIM;
                    Hl = g_Hsl + (size_t)z * T_TOK * F_DIM;
                } else { Hh = g_Hrh; Hl = g_Hrl; }
                st_hilo(Hh, Hl, (size_t)r * F_DIM + cg, h0, h1);
                st_hilo(Hh, Hl, (size_t)(r + 8) * F_DIM + cg, h2, h3);
            } else if (MODE == MF2S) {
                float b0 = bias[cg] + bias[D_DIM + cg];
                float b1 = bias[cg + 1] + bias[D_DIM + cg + 1];
                float2 v;
                v.x = c0 + b0; v.y = c1 + b1;
                *(float2*)&outF[(size_t)r * D_DIM + cg] = v;
                v.x = c2 + b0; v.y = c3 + b1;
                *(float2*)&outF[(size_t)(r + 8) * D_DIM + cg] = v;
            } else {  // MF2R
                float b0 = bias[z * D_DIM + cg], b1 = bias[z * D_DIM + cg + 1];
                float2 v;
                v.x = c0 + b0; v.y = c1 + b1;
                *(float2*)&g_Or[(size_t)r * D_DIM + cg] = v;
                v.x = c2 + b0; v.y = c3 + b1;
                *(float2*)&g_Or[(size_t)(r + 8) * D_DIM + cg] = v;
            }
        }
    }
}

// ---- combine routed contributions into out ----
__global__ void k_combine(float* __restrict__ out) {
    int idx = blockIdx.x * blockDim.x + threadIdx.x;
    if (idx >= T_TOK * (D_DIM / 4)) return;
    int t = idx >> 7;            // D/4 = 128
    int dq = idx & 127;
    float4 o = ((float4*)out)[t * 128 + dq];
    int r0 = g_rows[t * 2 + 0], r1 = g_rows[t * 2 + 1];
    float w0 = g_wt[t * 2 + 0], w1 = g_wt[t * 2 + 1];
    float4 a = ((const float4*)g_Or)[r0 * 128 + dq];
    float4 b = ((const float4*)g_Or)[r1 * 128 + dq];
    o.x += w0 * a.x + w1 * b.x;
    o.y += w0 * a.y + w1 * b.y;
    o.z += w0 * a.z + w1 * b.z;
    o.w += w0 * a.w + w1 * b.w;
    ((float4*)out)[t * 128 + dq] = o;
}

static inline void cvt(const float* s, __nv_bfloat16* h, __nv_bfloat16* l, int n) {
    int n4 = n / 4;
    k_cvt<<<(n4 + 255) / 256, 256>>>((const float4*)s, (__nv_bfloat162*)h,
                                     (__nv_bfloat162*)l, n4);
}

extern "C" void kernel_launch(void* const* d_in, const int* in_sizes, int n_in,
                              void* d_out, int out_size) {
    const float* x   = (const float*)d_in[0];
    const float* gw  = (const float*)d_in[1];
    const float* gb  = (const float*)d_in[2];
    const float* sw1 = (const float*)d_in[3];
    const float* sb1 = (const float*)d_in[4];
    const float* sw2 = (const float*)d_in[5];
    const float* sb2 = (const float*)d_in[6];
    const float* rw1 = (const float*)d_in[7];
    const float* rb1 = (const float*)d_in[8];
    const float* rw2 = (const float*)d_in[9];
    const float* rb2 = (const float*)d_in[10];
    float* out = (float*)d_out;

    __nv_bfloat16 *xh, *xl, *w1sh, *w1sl, *w2sh, *w2sl, *w1rh, *w1rl, *w2rh, *w2rl;
    cudaGetSymbolAddress((void**)&xh,   g_xh);   cudaGetSymbolAddress((void**)&xl,   g_xl);
    cudaGetSymbolAddress((void**)&w1sh, g_w1sh); cudaGetSymbolAddress((void**)&w1sl, g_w1sl);
    cudaGetSymbolAddress((void**)&w2sh, g_w2sh); cudaGetSymbolAddress((void**)&w2sl, g_w2sl);
    cudaGetSymbolAddress((void**)&w1rh, g_w1rh); cudaGetSymbolAddress((void**)&w1rl, g_w1rl);
    cudaGetSymbolAddress((void**)&w2rh, g_w2rh); cudaGetSymbolAddress((void**)&w2rl, g_w2rl);
    __nv_bfloat16 *Hsh, *Hsl, *Hrh, *Hrl;
    cudaGetSymbolAddress((void**)&Hsh, g_Hsh); cudaGetSymbolAddress((void**)&Hsl, g_Hsl);
    cudaGetSymbolAddress((void**)&Hrh, g_Hrh); cudaGetSymbolAddress((void**)&Hrl, g_Hrl);

    k_init<<<(ROWS_CAP + 255) / 256, 256>>>();
    cvt(x,   xh,   xl,   T_TOK * D_DIM);
    cvt(sw1, w1sh, w1sl, NS_SH * F_DIM * D_DIM);
    cvt(sw2, w2sh, w2sl, NS_SH * D_DIM * F_DIM);
    cvt(rw1, w1rh, w1rl, E_EXP * F_DIM * D_DIM);
    cvt(rw2, w2rh, w2rl, E_EXP * D_DIM * F_DIM);

    k_router<<<T_TOK / 8, 256>>>(x, gw, gb);
    k_scan<<<1, 1>>>();
    k_assign<<<(T_TOK + 255) / 256, 256>>>();

    dim3 blk(256);
    // FFN1 shared: M=T, N=F, K=D
    k_gemm<MF1S><<<dim3(F_DIM / BN, T_TOK / BM, NS_SH), blk>>>(xh, xl, w1sh, w1sl, sb1, nullptr);
    // FFN1 routed: padded rows, N=F, K=D
    k_gemm<MF1R><<<dim3(F_DIM / BN, 2 * T_TOK / BM, E_EXP), blk>>>(xh, xl, w1rh, w1rl, rb1, nullptr);
    // FFN2 shared: M=T, N=D, K=NS*F
    k_gemm<MF2S><<<dim3(D_DIM / BN, T_TOK / BM, 1), blk>>>(Hsh, Hsl, w2sh, w2sl, sb2, out);
    // FFN2 routed: padded rows, N=D, K=F
    k_gemm<MF2R><<<dim3(D_DIM / BN, 2 * T_TOK / BM, E_EXP), blk>>>(Hrh, Hrl, w2rh, w2rl, rb2, nullptr);
    // combine
    k_combine<<<(T_TOK * (D_DIM / 4) + 255) / 256, 256>>>(out);
}

// round 7
// speedup vs baseline: 6.5246x; 1.7653x over previous
#include <cuda_runtime.h>
#include <cuda_fp16.h>
#include <math.h>
#include <stdint.h>

// Problem constants
#define T_TOK 4096
#define D_DIM 512
#define F_DIM 2048
#define E_EXP 8
#define NS_SH 2
#define TOPK 2

// GEMM tiling
#define BM 128
#define BN 128
#define CK 64                         // K elems per chunk (128B fp16 rows)
#define STAGES 3
#define PLANE_B 16384                 // 128 rows * 128 B
#define STAGE_B (3*PLANE_B)           // Ah, Al, Bh
#define DSMEM_B (STAGES*STAGE_B)      // 147456

#define ROWS_CAP (2*T_TOK + E_EXP*BM) // 9216 padded routed rows

// ---- device scratch (allocation-free rule: __device__ globals) ----
__device__ __align__(128) __half g_xh [T_TOK*D_DIM],        g_xl [T_TOK*D_DIM];
__device__ __align__(128) __half g_w1s[NS_SH*F_DIM*D_DIM];
__device__ __align__(128) __half g_w2s[NS_SH*D_DIM*F_DIM];
__device__ __align__(128) __half g_w1r[E_EXP*F_DIM*D_DIM];
__device__ __align__(128) __half g_w2r[E_EXP*D_DIM*F_DIM];
__device__ __align__(128) __half g_Hsh[NS_SH*T_TOK*F_DIM],  g_Hsl[NS_SH*T_TOK*F_DIM];
__device__ __align__(128) __half g_Hrh[ROWS_CAP*F_DIM],     g_Hrl[ROWS_CAP*F_DIM];
__device__ __align__(128) float g_Or[ROWS_CAP*D_DIM];
// routing state
__device__ int   g_counts[E_EXP];
__device__ int   g_poff[E_EXP + 1];
__device__ int   g_cursor[E_EXP];
__device__ int   g_ntiles[E_EXP];
__device__ int   g_eid[T_TOK * TOPK];
__device__ float g_wt[T_TOK * TOPK];
__device__ int   g_rows[T_TOK * TOPK];
__device__ int   g_row_token[ROWS_CAP];

__device__ __forceinline__ float gelu_exact(float v) {
    return 0.5f * v * (1.0f + erff(v * 0.70710678118654752440f));
}

// ================= PTX helpers (all sm_90-safe) =================
__device__ __forceinline__ uint32_t smem_u32(const void* p) {
    uint32_t a;
    asm("{ .reg .u64 t; cvta.to.shared.u64 t, %1; cvt.u32.u64 %0, t; }" : "=r"(a) : "l"(p));
    return a;
}
__device__ __forceinline__ void cp16(uint32_t s, const void* g) {
    asm volatile("cp.async.cg.shared.global [%0], [%1], 16;\n" :: "r"(s), "l"(g));
}
__device__ __forceinline__ void cp_commit() {
    asm volatile("cp.async.commit_group;\n" ::: "memory");
}
__device__ __forceinline__ void ldsm4(uint32_t& r0, uint32_t& r1, uint32_t& r2, uint32_t& r3,
                                      uint32_t addr) {
    asm volatile("ldmatrix.sync.aligned.m8n8.x4.shared.b16 {%0,%1,%2,%3}, [%4];"
                 : "=r"(r0), "=r"(r1), "=r"(r2), "=r"(r3) : "r"(addr));
}
__device__ __forceinline__ void mma_f16(float& c0, float& c1, float& c2, float& c3,
                                        uint32_t a0, uint32_t a1, uint32_t a2, uint32_t a3,
                                        uint32_t b0, uint32_t b1) {
    asm volatile(
        "mma.sync.aligned.m16n8k16.row.col.f32.f16.f16.f32 "
        "{%0,%1,%2,%3},{%4,%5,%6,%7},{%8,%9},{%0,%1,%2,%3};\n"
        : "+f"(c0), "+f"(c1), "+f"(c2), "+f"(c3)
        : "r"(a0), "r"(a1), "r"(a2), "r"(a3), "r"(b0), "r"(b1));
}

// ---- K0: reset per-call state ----
__global__ void k_init() {
    int i = blockIdx.x * blockDim.x + threadIdx.x;
    if (i < E_EXP) g_counts[i] = 0;
    if (i < ROWS_CAP) g_row_token[i] = 0;
}

// ---- fp32 -> fp16 hi/lo split ----
__global__ void k_cvt2(const float4* __restrict__ s,
                       __half2* __restrict__ h, __half2* __restrict__ l, int n4) {
    int i = blockIdx.x * blockDim.x + threadIdx.x;
    if (i >= n4) return;
    float4 v = s[i];
    __half h0 = __float2half_rn(v.x), h1 = __float2half_rn(v.y);
    __half h2 = __float2half_rn(v.z), h3 = __float2half_rn(v.w);
    h[2*i]   = __halves2half2(h0, h1);
    h[2*i+1] = __halves2half2(h2, h3);
    l[2*i]   = __halves2half2(__float2half_rn(v.x - __half2float(h0)),
                              __float2half_rn(v.y - __half2float(h1)));
    l[2*i+1] = __halves2half2(__float2half_rn(v.z - __half2float(h2)),
                              __float2half_rn(v.w - __half2float(h3)));
}
// ---- fp32 -> fp16 single round ----
__global__ void k_cvt1(const float4* __restrict__ s, __half2* __restrict__ h, int n4) {
    int i = blockIdx.x * blockDim.x + threadIdx.x;
    if (i >= n4) return;
    float4 v = s[i];
    h[2*i]   = __halves2half2(__float2half_rn(v.x), __float2half_rn(v.y));
    h[2*i+1] = __halves2half2(__float2half_rn(v.z), __float2half_rn(v.w));
}

// ---- K1: router (one warp per token) ----
__global__ void k_router(const float* __restrict__ x,
                         const float* __restrict__ gw,
                         const float* __restrict__ gb) {
    int warp = (blockIdx.x * blockDim.x + threadIdx.x) >> 5;
    int lane = threadIdx.x & 31;
    if (warp >= T_TOK) return;
    const float* xr = x + warp * D_DIM;
    float xv[16];
#pragma unroll
    for (int i = 0; i < 16; i++) xv[i] = xr[lane + 32 * i];
    float acc[E_EXP];
#pragma unroll
    for (int e = 0; e < E_EXP; e++) acc[e] = 0.f;
#pragma unroll
    for (int i = 0; i < 16; i++) {
        int d = lane + 32 * i;
#pragma unroll
        for (int e = 0; e < E_EXP; e++) acc[e] += xv[i] * gw[e * D_DIM + d];
    }
#pragma unroll
    for (int e = 0; e < E_EXP; e++) {
#pragma unroll
        for (int off = 16; off; off >>= 1)
            acc[e] += __shfl_xor_sync(0xffffffffu, acc[e], off);
    }
    if (lane == 0) {
        float lg[E_EXP], mx = -1e30f;
#pragma unroll
        for (int e = 0; e < E_EXP; e++) { lg[e] = acc[e] + gb[e]; mx = fmaxf(mx, lg[e]); }
        float s = 0.f;
#pragma unroll
        for (int e = 0; e < E_EXP; e++) { lg[e] = expf(lg[e] - mx); s += lg[e]; }
        float inv = 1.f / s;
#pragma unroll
        for (int e = 0; e < E_EXP; e++) lg[e] *= inv;
        int i1 = 0; float v1 = -1.f;
#pragma unroll
        for (int e = 0; e < E_EXP; e++) { if (lg[e] > v1) { v1 = lg[e]; i1 = e; } }
        int i2 = -1; float v2 = -1.f;
#pragma unroll
        for (int e = 0; e < E_EXP; e++) { if (e != i1 && lg[e] > v2) { v2 = lg[e]; i2 = e; } }
        g_eid[warp * 2 + 0] = i1;  g_wt[warp * 2 + 0] = v1;
        g_eid[warp * 2 + 1] = i2;  g_wt[warp * 2 + 1] = v2;
        atomicAdd(&g_counts[i1], 1);
        atomicAdd(&g_counts[i2], 1);
    }
}

// ---- K2: scan -> padded segments (pad to BM) ----
__global__ void k_scan() {
    int off = 0;
    for (int e = 0; e < E_EXP; e++) {
        g_poff[e] = off;
        g_cursor[e] = off;
        int nt = (g_counts[e] + BM - 1) / BM;
        g_ntiles[e] = nt;
        off += nt * BM;
    }
    g_poff[E_EXP] = off;
}

// ---- K3: assign rows ----
__global__ void k_assign() {
    int t = blockIdx.x * blockDim.x + threadIdx.x;
    if (t >= T_TOK) return;
#pragma unroll
    for (int k = 0; k < TOPK; k++) {
        int e = g_eid[t * 2 + k];
        int r = atomicAdd(&g_cursor[e], 1);
        g_rows[t * 2 + k] = r;
        g_row_token[r] = t;
    }
}

// ==================== mma.sync GEMM (fp16 2-mma: A hi/lo, B single) ====================
// C[M,N] = A[M,K] * B[N,K]^T, K-contiguous operands, fp32 accumulate.
enum { MF1S = 0, MF1R = 1, MF2S = 2, MF2R = 3 };

template<int MODE>
__global__ void __launch_bounds__(256) k_mma(
    const __half* __restrict__ Ah, const __half* __restrict__ Al,
    const __half* __restrict__ Bp,
    const float* __restrict__ bias, float* __restrict__ outF) {
    int z = blockIdx.z;
    int row0;
    if (MODE == MF1R || MODE == MF2R) {
        if ((int)blockIdx.y >= g_ntiles[z]) return;
        row0 = g_poff[z] + blockIdx.y * BM;
    } else {
        row0 = blockIdx.y * BM;
    }
    int col0 = blockIdx.x * BN;

    const int KA = (MODE == MF1S || MODE == MF1R) ? D_DIM : F_DIM;
    const int NK = (MODE == MF2S) ? (NS_SH * F_DIM) / CK : KA / CK;

    const __half* B0 = Bp;
    if (MODE == MF1S || MODE == MF1R) B0 += (size_t)z * F_DIM * D_DIM;
    if (MODE == MF2R)                 B0 += (size_t)z * D_DIM * F_DIM;

    extern __shared__ __align__(128) char dsm[];
    __shared__ int s_tok[BM];
    uint32_t sbase = smem_u32(dsm);

    int tid = threadIdx.x, wid = tid >> 5, lane = tid & 31;

    if (MODE == MF1R) {
        for (int i = tid; i < BM; i += 256) s_tok[i] = g_row_token[row0 + i];
        __syncthreads();
    }

    auto load_chunk = [&](int ci) {
        uint32_t sb = sbase + (ci % STAGES) * STAGE_B;
        int k0 = ci * CK, kk = k0;
        const __half *pAh = Ah, *pAl = Al, *pB = B0;
        if (MODE == MF2S) {
            int pl = k0 >> 11; kk = k0 & (F_DIM - 1);
            size_t ao = (size_t)pl * T_TOK * F_DIM, bo = (size_t)pl * D_DIM * F_DIM;
            pAh += ao; pAl += ao; pB += bo;
        }
#pragma unroll
        for (int j = 0; j < 4; j++) {
            int idx = tid + j * 256;            // 0..1023
            int r = idx >> 3, u = idx & 7;
            uint32_t so = r * 128 + ((u ^ (r & 7)) * 16);
            int ar = (MODE == MF1R) ? s_tok[r] : (row0 + r);
            size_t goA = (size_t)ar * KA + kk + u * 8;
            cp16(sb + so,               pAh + goA);
            cp16(sb + PLANE_B + so,     pAl + goA);
            cp16(sb + 2 * PLANE_B + so, pB + (size_t)(col0 + r) * KA + kk + u * 8);
        }
        cp_commit();
    };

    // warp layout: 2x4 grid of 64x32 warp tiles
    int wr = (wid >> 2) * 64, wc = (wid & 3) * 32;
    int grp = lane >> 2, qp = lane & 3;
    int rl = lane & 15, hi = lane >> 4;

    float c[4][4][4];
#pragma unroll
    for (int i = 0; i < 4; i++)
#pragma unroll
        for (int j = 0; j < 4; j++)
#pragma unroll
            for (int q = 0; q < 4; q++) c[i][j][q] = 0.f;

    int npre = NK < STAGES ? NK : STAGES;
    for (int ci = 0; ci < npre; ci++) load_chunk(ci);

    for (int i = 0; i < NK; i++) {
        int issued = (NK < i + STAGES) ? NK : (i + STAGES);
        int pend = issued - i - 1;
        if (pend >= 2)      asm volatile("cp.async.wait_group 2;" ::: "memory");
        else if (pend == 1) asm volatile("cp.async.wait_group 1;" ::: "memory");
        else                asm volatile("cp.async.wait_group 0;" ::: "memory");
        __syncthreads();
        uint32_t sb = sbase + (i % STAGES) * STAGE_B;

#pragma unroll
        for (int ks = 0; ks < 4; ks++) {
            int cch = 2 * ks + hi;
            uint32_t ah[4][4], al[4][4], bq[4][2];
#pragma unroll
            for (int mt = 0; mt < 4; mt++) {
                int r = wr + mt * 16 + rl;
                uint32_t ad = sb + r * 128 + ((cch ^ (r & 7)) << 4);
                ldsm4(ah[mt][0], ah[mt][1], ah[mt][2], ah[mt][3], ad);
                ldsm4(al[mt][0], al[mt][1], al[mt][2], al[mt][3], ad + PLANE_B);
            }
#pragma unroll
            for (int p = 0; p < 2; p++) {
                int r = wc + p * 16 + rl;
                uint32_t ad = sb + 2 * PLANE_B + r * 128 + ((cch ^ (r & 7)) << 4);
                uint32_t q0, q1, q2, q3;
                ldsm4(q0, q1, q2, q3, ad);
                bq[2*p][0] = q0; bq[2*p+1][0] = q1;
                bq[2*p][1] = q2; bq[2*p+1][1] = q3;
            }
#pragma unroll
            for (int mt = 0; mt < 4; mt++)
#pragma unroll
                for (int nt = 0; nt < 4; nt++) {
                    mma_f16(c[mt][nt][0], c[mt][nt][1], c[mt][nt][2], c[mt][nt][3],
                            ah[mt][0], ah[mt][1], ah[mt][2], ah[mt][3],
                            bq[nt][0], bq[nt][1]);
                    mma_f16(c[mt][nt][0], c[mt][nt][1], c[mt][nt][2], c[mt][nt][3],
                            al[mt][0], al[mt][1], al[mt][2], al[mt][3],
                            bq[nt][0], bq[nt][1]);
                }
        }
        __syncthreads();
        if (i + STAGES < NK) load_chunk(i + STAGES);
    }

    // ---- epilogue ----
#pragma unroll
    for (int mt = 0; mt < 4; ++mt) {
        int r = row0 + wr + mt * 16 + grp;
#pragma unroll
        for (int nt = 0; nt < 4; ++nt) {
            int cg = col0 + wc + nt * 8 + qp * 2;
            float c0 = c[mt][nt][0], c1 = c[mt][nt][1];
            float c2 = c[mt][nt][2], c3 = c[mt][nt][3];
            if (MODE == MF1S || MODE == MF1R) {
                const float* bz = bias + (size_t)z * F_DIM;
                float b0 = bz[cg], b1 = bz[cg + 1];
                float h0 = gelu_exact(c0 + b0), h1 = gelu_exact(c1 + b1);
                float h2 = gelu_exact(c2 + b0), h3 = gelu_exact(c3 + b1);
                __half* Hh; __half* Hl;
                if (MODE == MF1S) {
                    Hh = g_Hsh + (size_t)z * T_TOK * F_DIM;
                    Hl = g_Hsl + (size_t)z * T_TOK * F_DIM;
                } else { Hh = g_Hrh; Hl = g_Hrl; }
                __half p0 = __float2half_rn(h0), p1 = __float2half_rn(h1);
                __half p2 = __float2half_rn(h2), p3 = __float2half_rn(h3);
                *(__half2*)(Hh + (size_t)r * F_DIM + cg)       = __halves2half2(p0, p1);
                *(__half2*)(Hh + (size_t)(r + 8) * F_DIM + cg) = __halves2half2(p2, p3);
                *(__half2*)(Hl + (size_t)r * F_DIM + cg) =
                    __halves2half2(__float2half_rn(h0 - __half2float(p0)),
                                   __float2half_rn(h1 - __half2float(p1)));
                *(__half2*)(Hl + (size_t)(r + 8) * F_DIM + cg) =
                    __halves2half2(__float2half_rn(h2 - __half2float(p2)),
                                   __float2half_rn(h3 - __half2float(p3)));
            } else if (MODE == MF2S) {
                float b0 = bias[cg] + bias[D_DIM + cg];
                float b1 = bias[cg + 1] + bias[D_DIM + cg + 1];
                float2 v;
                v.x = c0 + b0; v.y = c1 + b1;
                *(float2*)&outF[(size_t)r * D_DIM + cg] = v;
                v.x = c2 + b0; v.y = c3 + b1;
                *(float2*)&outF[(size_t)(r + 8) * D_DIM + cg] = v;
            } else {  // MF2R
                const float* bz = bias + (size_t)z * D_DIM;
                float b0 = bz[cg], b1 = bz[cg + 1];
                float2 v;
                v.x = c0 + b0; v.y = c1 + b1;
                *(float2*)&g_Or[(size_t)r * D_DIM + cg] = v;
                v.x = c2 + b0; v.y = c3 + b1;
                *(float2*)&g_Or[(size_t)(r + 8) * D_DIM + cg] = v;
            }
        }
    }
}

// ---- combine routed contributions into out ----
__global__ void k_combine(float* __restrict__ out) {
    int idx = blockIdx.x * blockDim.x + threadIdx.x;
    if (idx >= T_TOK * (D_DIM / 4)) return;
    int t = idx >> 7;
    int dq = idx & 127;
    float4 o = ((float4*)out)[t * 128 + dq];
    int r0 = g_rows[t * 2 + 0], r1 = g_rows[t * 2 + 1];
    float w0 = g_wt[t * 2 + 0], w1 = g_wt[t * 2 + 1];
    float4 a = ((const float4*)g_Or)[(size_t)r0 * 128 + dq];
    float4 b = ((const float4*)g_Or)[(size_t)r1 * 128 + dq];
    o.x += w0 * a.x + w1 * b.x;
    o.y += w0 * a.y + w1 * b.y;
    o.z += w0 * a.z + w1 * b.z;
    o.w += w0 * a.w + w1 * b.w;
    ((float4*)out)[t * 128 + dq] = o;
}

extern "C" void kernel_launch(void* const* d_in, const int* in_sizes, int n_in,
                              void* d_out, int out_size) {
    const float* x   = (const float*)d_in[0];
    const float* gw  = (const float*)d_in[1];
    const float* gb  = (const float*)d_in[2];
    const float* sw1 = (const float*)d_in[3];
    const float* sb1 = (const float*)d_in[4];
    const float* sw2 = (const float*)d_in[5];
    const float* sb2 = (const float*)d_in[6];
    const float* rw1 = (const float*)d_in[7];
    const float* rb1 = (const float*)d_in[8];
    const float* rw2 = (const float*)d_in[9];
    const float* rb2 = (const float*)d_in[10];
    float* out = (float*)d_out;

    __half *xh, *xl, *w1s, *w2s, *w1r, *w2r, *Hsh, *Hsl, *Hrh, *Hrl;
    cudaGetSymbolAddress((void**)&xh,  g_xh);  cudaGetSymbolAddress((void**)&xl,  g_xl);
    cudaGetSymbolAddress((void**)&w1s, g_w1s); cudaGetSymbolAddress((void**)&w2s, g_w2s);
    cudaGetSymbolAddress((void**)&w1r, g_w1r); cudaGetSymbolAddress((void**)&w2r, g_w2r);
    cudaGetSymbolAddress((void**)&Hsh, g_Hsh); cudaGetSymbolAddress((void**)&Hsl, g_Hsl);
    cudaGetSymbolAddress((void**)&Hrh, g_Hrh); cudaGetSymbolAddress((void**)&Hrl, g_Hrl);

    static int smem_set = 0;
    if (!smem_set) {
        cudaFuncSetAttribute(k_mma<MF1S>, cudaFuncAttributeMaxDynamicSharedMemorySize, DSMEM_B);
        cudaFuncSetAttribute(k_mma<MF1R>, cudaFuncAttributeMaxDynamicSharedMemorySize, DSMEM_B);
        cudaFuncSetAttribute(k_mma<MF2S>, cudaFuncAttributeMaxDynamicSharedMemorySize, DSMEM_B);
        cudaFuncSetAttribute(k_mma<MF2R>, cudaFuncAttributeMaxDynamicSharedMemorySize, DSMEM_B);
        smem_set = 1;
    }

    k_init<<<(ROWS_CAP + 255) / 256, 256>>>();
    {
        int n4;
        n4 = (T_TOK * D_DIM) / 4;
        k_cvt2<<<(n4 + 255) / 256, 256>>>((const float4*)x, (__half2*)xh, (__half2*)xl, n4);
        n4 = (NS_SH * F_DIM * D_DIM) / 4;
        k_cvt1<<<(n4 + 255) / 256, 256>>>((const float4*)sw1, (__half2*)w1s, n4);
        n4 = (NS_SH * D_DIM * F_DIM) / 4;
        k_cvt1<<<(n4 + 255) / 256, 256>>>((const float4*)sw2, (__half2*)w2s, n4);
        n4 = (E_EXP * F_DIM * D_DIM) / 4;
        k_cvt1<<<(n4 + 255) / 256, 256>>>((const float4*)rw1, (__half2*)w1r, n4);
        n4 = (E_EXP * D_DIM * F_DIM) / 4;
        k_cvt1<<<(n4 + 255) / 256, 256>>>((const float4*)rw2, (__half2*)w2r, n4);
    }

    k_router<<<T_TOK / 8, 256>>>(x, gw, gb);
    k_scan<<<1, 1>>>();
    k_assign<<<(T_TOK + 255) / 256, 256>>>();

    dim3 blk(256);
    // FFN1 shared: M=T, N=F, K=D
    k_mma<MF1S><<<dim3(F_DIM / BN, T_TOK / BM, NS_SH), blk, DSMEM_B>>>(xh, xl, w1s, sb1, nullptr);
    // FFN1 routed: padded rows (<=32 tiles/expert), N=F, K=D
    k_mma<MF1R><<<dim3(F_DIM / BN, T_TOK / BM, E_EXP), blk, DSMEM_B>>>(xh, xl, w1r, rb1, nullptr);
    // FFN2 shared: M=T, N=D, K=NS*F
    k_mma<MF2S><<<dim3(D_DIM / BN, T_TOK / BM, 1),     blk, DSMEM_B>>>(Hsh, Hsl, w2s, sb2, out);
    // FFN2 routed: padded rows, N=D, K=F
    k_mma<MF2R><<<dim3(D_DIM / BN, T_TOK / BM, E_EXP), blk, DSMEM_B>>>(Hrh, Hrl, w2r, rb2, nullptr);
    // combine
    k_combine<<<(T_TOK * (D_DIM / 4) + 255) / 256, 256>>>(out);
}

// round 8
// speedup vs baseline: 7.7342x; 1.1854x over previous
#include <cuda_runtime.h>
#include <cuda_fp16.h>
#include <math.h>
#include <stdint.h>

// Problem constants
#define T_TOK 4096
#define D_DIM 512
#define F_DIM 2048
#define E_EXP 8
#define NS_SH 2
#define TOPK 2

// GEMM tiling
#define BM 128
#define BN 128
#define CK 64                         // K elems per chunk (128B fp16 rows)
#define STAGES 3
#define PLANE_B 16384                 // 128 rows * 128 B
#define STAGE_B (2*PLANE_B)           // A, B
#define DSMEM_B (STAGES*STAGE_B)      // 98304

#define ROWS_CAP (2*T_TOK + E_EXP*BM) // 9216 padded routed rows

// ---- device scratch (allocation-free rule: __device__ globals) ----
__device__ __align__(128) __half g_x  [T_TOK*D_DIM];
__device__ __align__(128) __half g_w1s[NS_SH*F_DIM*D_DIM];
__device__ __align__(128) __half g_w2s[NS_SH*D_DIM*F_DIM];
__device__ __align__(128) __half g_w1r[E_EXP*F_DIM*D_DIM];
__device__ __align__(128) __half g_w2r[E_EXP*D_DIM*F_DIM];
__device__ __align__(128) __half g_Hs [NS_SH*T_TOK*F_DIM];
__device__ __align__(128) __half g_Hr [ROWS_CAP*F_DIM];
__device__ __align__(128) float g_Or[ROWS_CAP*D_DIM];
// routing state
__device__ int   g_counts[E_EXP];
__device__ int   g_poff[E_EXP + 1];
__device__ int   g_cursor[E_EXP];
__device__ int   g_ntiles[E_EXP];
__device__ int   g_eid[T_TOK * TOPK];
__device__ float g_wt[T_TOK * TOPK];
__device__ int   g_rows[T_TOK * TOPK];
__device__ int   g_row_token[ROWS_CAP];

__device__ __forceinline__ float gelu_exact(float v) {
    return 0.5f * v * (1.0f + erff(v * 0.70710678118654752440f));
}

// ================= PTX helpers =================
__device__ __forceinline__ uint32_t smem_u32(const void* p) {
    uint32_t a;
    asm("{ .reg .u64 t; cvta.to.shared.u64 t, %1; cvt.u32.u64 %0, t; }" : "=r"(a) : "l"(p));
    return a;
}
__device__ __forceinline__ void cp16(uint32_t s, const void* g) {
    asm volatile("cp.async.cg.shared.global [%0], [%1], 16;\n" :: "r"(s), "l"(g));
}
__device__ __forceinline__ void cp_commit() {
    asm volatile("cp.async.commit_group;\n" ::: "memory");
}
__device__ __forceinline__ void ldsm4(uint32_t& r0, uint32_t& r1, uint32_t& r2, uint32_t& r3,
                                      uint32_t addr) {
    asm volatile("ldmatrix.sync.aligned.m8n8.x4.shared.b16 {%0,%1,%2,%3}, [%4];"
                 : "=r"(r0), "=r"(r1), "=r"(r2), "=r"(r3) : "r"(addr));
}
__device__ __forceinline__ void mma_f16(float& c0, float& c1, float& c2, float& c3,
                                        uint32_t a0, uint32_t a1, uint32_t a2, uint32_t a3,
                                        uint32_t b0, uint32_t b1) {
    asm volatile(
        "mma.sync.aligned.m16n8k16.row.col.f32.f16.f16.f32 "
        "{%0,%1,%2,%3},{%4,%5,%6,%7},{%8,%9},{%0,%1,%2,%3};\n"
        : "+f"(c0), "+f"(c1), "+f"(c2), "+f"(c3)
        : "r"(a0), "r"(a1), "r"(a2), "r"(a3), "r"(b0), "r"(b1));
}

// ---- K0: reset per-call state ----
__global__ void k_init() {
    int i = blockIdx.x * blockDim.x + threadIdx.x;
    if (i < E_EXP) g_counts[i] = 0;
    if (i < ROWS_CAP) g_row_token[i] = 0;
}

// ---- fp32 -> fp16 round ----
__global__ void k_cvt1(const float4* __restrict__ s, __half2* __restrict__ h, int n4) {
    int i = blockIdx.x * blockDim.x + threadIdx.x;
    if (i >= n4) return;
    float4 v = s[i];
    h[2*i]   = __halves2half2(__float2half_rn(v.x), __float2half_rn(v.y));
    h[2*i+1] = __halves2half2(__float2half_rn(v.z), __float2half_rn(v.w));
}

// ---- K1: router (one warp per token) ----
__global__ void k_router(const float* __restrict__ x,
                         const float* __restrict__ gw,
                         const float* __restrict__ gb) {
    int warp = (blockIdx.x * blockDim.x + threadIdx.x) >> 5;
    int lane = threadIdx.x & 31;
    if (warp >= T_TOK) return;
    const float* xr = x + warp * D_DIM;
    float xv[16];
#pragma unroll
    for (int i = 0; i < 16; i++) xv[i] = xr[lane + 32 * i];
    float acc[E_EXP];
#pragma unroll
    for (int e = 0; e < E_EXP; e++) acc[e] = 0.f;
#pragma unroll
    for (int i = 0; i < 16; i++) {
        int d = lane + 32 * i;
#pragma unroll
        for (int e = 0; e < E_EXP; e++) acc[e] += xv[i] * gw[e * D_DIM + d];
    }
#pragma unroll
    for (int e = 0; e < E_EXP; e++) {
#pragma unroll
        for (int off = 16; off; off >>= 1)
            acc[e] += __shfl_xor_sync(0xffffffffu, acc[e], off);
    }
    if (lane == 0) {
        float lg[E_EXP], mx = -1e30f;
#pragma unroll
        for (int e = 0; e < E_EXP; e++) { lg[e] = acc[e] + gb[e]; mx = fmaxf(mx, lg[e]); }
        float s = 0.f;
#pragma unroll
        for (int e = 0; e < E_EXP; e++) { lg[e] = expf(lg[e] - mx); s += lg[e]; }
        float inv = 1.f / s;
#pragma unroll
        for (int e = 0; e < E_EXP; e++) lg[e] *= inv;
        int i1 = 0; float v1 = -1.f;
#pragma unroll
        for (int e = 0; e < E_EXP; e++) { if (lg[e] > v1) { v1 = lg[e]; i1 = e; } }
        int i2 = -1; float v2 = -1.f;
#pragma unroll
        for (int e = 0; e < E_EXP; e++) { if (e != i1 && lg[e] > v2) { v2 = lg[e]; i2 = e; } }
        g_eid[warp * 2 + 0] = i1;  g_wt[warp * 2 + 0] = v1;
        g_eid[warp * 2 + 1] = i2;  g_wt[warp * 2 + 1] = v2;
        atomicAdd(&g_counts[i1], 1);
        atomicAdd(&g_counts[i2], 1);
    }
}

// ---- K2: scan -> padded segments ----
__global__ void k_scan() {
    int off = 0;
    for (int e = 0; e < E_EXP; e++) {
        g_poff[e] = off;
        g_cursor[e] = off;
        int nt = (g_counts[e] + BM - 1) / BM;
        g_ntiles[e] = nt;
        off += nt * BM;
    }
    g_poff[E_EXP] = off;
}

// ---- K3: assign rows ----
__global__ void k_assign() {
    int t = blockIdx.x * blockDim.x + threadIdx.x;
    if (t >= T_TOK) return;
#pragma unroll
    for (int k = 0; k < TOPK; k++) {
        int e = g_eid[t * 2 + k];
        int r = atomicAdd(&g_cursor[e], 1);
        g_rows[t * 2 + k] = r;
        g_row_token[r] = t;
    }
}

// ==================== mma.sync GEMM (single fp16) ====================
// C[M,N] = A[M,K] * B[N,K]^T, K-contiguous operands, fp32 accumulate.
enum { MF1S = 0, MF1R = 1, MF2S = 2, MF2R = 3 };

template<int MODE>
__global__ void __launch_bounds__(256) k_mma(
    const __half* __restrict__ Ap, const __half* __restrict__ Bp,
    const float* __restrict__ bias, float* __restrict__ outF) {
    int z = blockIdx.z;
    int row0;
    if (MODE == MF1R || MODE == MF2R) {
        if ((int)blockIdx.y >= g_ntiles[z]) return;
        row0 = g_poff[z] + blockIdx.y * BM;
    } else {
        row0 = blockIdx.y * BM;
    }
    int col0 = blockIdx.x * BN;

    const int KA = (MODE == MF1S || MODE == MF1R) ? D_DIM : F_DIM;
    const int NK = (MODE == MF2S) ? (NS_SH * F_DIM) / CK : KA / CK;

    const __half* B0 = Bp;
    if (MODE == MF1S || MODE == MF1R) B0 += (size_t)z * F_DIM * D_DIM;
    if (MODE == MF2R)                 B0 += (size_t)z * D_DIM * F_DIM;

    extern __shared__ __align__(128) char dsm[];
    __shared__ int s_tok[BM];
    uint32_t sbase = smem_u32(dsm);

    int tid = threadIdx.x, wid = tid >> 5, lane = tid & 31;

    if (MODE == MF1R) {
        for (int i = tid; i < BM; i += 256) s_tok[i] = g_row_token[row0 + i];
        __syncthreads();
    }

    auto load_chunk = [&](int ci) {
        uint32_t sb = sbase + (ci % STAGES) * STAGE_B;
        int k0 = ci * CK, kk = k0;
        const __half *pA = Ap, *pB = B0;
        if (MODE == MF2S) {
            int pl = k0 >> 11; kk = k0 & (F_DIM - 1);
            pA += (size_t)pl * T_TOK * F_DIM;
            pB += (size_t)pl * D_DIM * F_DIM;
        }
#pragma unroll
        for (int j = 0; j < 4; j++) {
            int idx = tid + j * 256;            // 0..1023
            int r = idx >> 3, u = idx & 7;
            uint32_t so = r * 128 + ((u ^ (r & 7)) * 16);
            int ar = (MODE == MF1R) ? s_tok[r] : (row0 + r);
            cp16(sb + so,           pA + (size_t)ar * KA + kk + u * 8);
            cp16(sb + PLANE_B + so, pB + (size_t)(col0 + r) * KA + kk + u * 8);
        }
        cp_commit();
    };

    // warp layout: 2x4 grid of 64x32 warp tiles
    int wr = (wid >> 2) * 64, wc = (wid & 3) * 32;
    int grp = lane >> 2, qp = lane & 3;
    int rl = lane & 15, hi = lane >> 4;

    float c[4][4][4];
#pragma unroll
    for (int i = 0; i < 4; i++)
#pragma unroll
        for (int j = 0; j < 4; j++)
#pragma unroll
            for (int q = 0; q < 4; q++) c[i][j][q] = 0.f;

    int npre = NK < STAGES ? NK : STAGES;
    for (int ci = 0; ci < npre; ci++) load_chunk(ci);

    for (int i = 0; i < NK; i++) {
        int issued = (NK < i + STAGES) ? NK : (i + STAGES);
        int pend = issued - i - 1;
        if (pend >= 2)      asm volatile("cp.async.wait_group 2;" ::: "memory");
        else if (pend == 1) asm volatile("cp.async.wait_group 1;" ::: "memory");
        else                asm volatile("cp.async.wait_group 0;" ::: "memory");
        __syncthreads();
        uint32_t sb = sbase + (i % STAGES) * STAGE_B;

#pragma unroll
        for (int ks = 0; ks < 4; ks++) {
            int cch = 2 * ks + hi;
            uint32_t ah[4][4], bq[4][2];
#pragma unroll
            for (int mt = 0; mt < 4; mt++) {
                int r = wr + mt * 16 + rl;
                uint32_t ad = sb + r * 128 + ((cch ^ (r & 7)) << 4);
                ldsm4(ah[mt][0], ah[mt][1], ah[mt][2], ah[mt][3], ad);
            }
#pragma unroll
            for (int p = 0; p < 2; p++) {
                int r = wc + p * 16 + rl;
                uint32_t ad = sb + PLANE_B + r * 128 + ((cch ^ (r & 7)) << 4);
                uint32_t q0, q1, q2, q3;
                ldsm4(q0, q1, q2, q3, ad);
                bq[2*p][0] = q0; bq[2*p+1][0] = q1;
                bq[2*p][1] = q2; bq[2*p+1][1] = q3;
            }
#pragma unroll
            for (int mt = 0; mt < 4; mt++)
#pragma unroll
                for (int nt = 0; nt < 4; nt++)
                    mma_f16(c[mt][nt][0], c[mt][nt][1], c[mt][nt][2], c[mt][nt][3],
                            ah[mt][0], ah[mt][1], ah[mt][2], ah[mt][3],
                            bq[nt][0], bq[nt][1]);
        }
        __syncthreads();
        if (i + STAGES < NK) load_chunk(i + STAGES);
    }

    // ---- epilogue ----
#pragma unroll
    for (int mt = 0; mt < 4; ++mt) {
        int r = row0 + wr + mt * 16 + grp;
#pragma unroll
        for (int nt = 0; nt < 4; ++nt) {
            int cg = col0 + wc + nt * 8 + qp * 2;
            float c0 = c[mt][nt][0], c1 = c[mt][nt][1];
            float c2 = c[mt][nt][2], c3 = c[mt][nt][3];
            if (MODE == MF1S || MODE == MF1R) {
                const float* bz = bias + (size_t)z * F_DIM;
                float b0 = bz[cg], b1 = bz[cg + 1];
                float h0 = gelu_exact(c0 + b0), h1 = gelu_exact(c1 + b1);
                float h2 = gelu_exact(c2 + b0), h3 = gelu_exact(c3 + b1);
                __half* Hh = (MODE == MF1S) ? (g_Hs + (size_t)z * T_TOK * F_DIM) : g_Hr;
                *(__half2*)(Hh + (size_t)r * F_DIM + cg) =
                    __halves2half2(__float2half_rn(h0), __float2half_rn(h1));
                *(__half2*)(Hh + (size_t)(r + 8) * F_DIM + cg) =
                    __halves2half2(__float2half_rn(h2), __float2half_rn(h3));
            } else if (MODE == MF2S) {
                float b0 = bias[cg] + bias[D_DIM + cg];
                float b1 = bias[cg + 1] + bias[D_DIM + cg + 1];
                float2 v;
                v.x = c0 + b0; v.y = c1 + b1;
                *(float2*)&outF[(size_t)r * D_DIM + cg] = v;
                v.x = c2 + b0; v.y = c3 + b1;
                *(float2*)&outF[(size_t)(r + 8) * D_DIM + cg] = v;
            } else {  // MF2R
                const float* bz = bias + (size_t)z * D_DIM;
                float b0 = bz[cg], b1 = bz[cg + 1];
                float2 v;
                v.x = c0 + b0; v.y = c1 + b1;
                *(float2*)&g_Or[(size_t)r * D_DIM + cg] = v;
                v.x = c2 + b0; v.y = c3 + b1;
                *(float2*)&g_Or[(size_t)(r + 8) * D_DIM + cg] = v;
            }
        }
    }
}

// ---- combine routed contributions into out ----
__global__ void k_combine(float* __restrict__ out) {
    int idx = blockIdx.x * blockDim.x + threadIdx.x;
    if (idx >= T_TOK * (D_DIM / 4)) return;
    int t = idx >> 7;
    int dq = idx & 127;
    float4 o = ((float4*)out)[t * 128 + dq];
    int r0 = g_rows[t * 2 + 0], r1 = g_rows[t * 2 + 1];
    float w0 = g_wt[t * 2 + 0], w1 = g_wt[t * 2 + 1];
    float4 a = ((const float4*)g_Or)[(size_t)r0 * 128 + dq];
    float4 b = ((const float4*)g_Or)[(size_t)r1 * 128 + dq];
    o.x += w0 * a.x + w1 * b.x;
    o.y += w0 * a.y + w1 * b.y;
    o.z += w0 * a.z + w1 * b.z;
    o.w += w0 * a.w + w1 * b.w;
    ((float4*)out)[t * 128 + dq] = o;
}

extern "C" void kernel_launch(void* const* d_in, const int* in_sizes, int n_in,
                              void* d_out, int out_size) {
    const float* x   = (const float*)d_in[0];
    const float* gw  = (const float*)d_in[1];
    const float* gb  = (const float*)d_in[2];
    const float* sw1 = (const float*)d_in[3];
    const float* sb1 = (const float*)d_in[4];
    const float* sw2 = (const float*)d_in[5];
    const float* sb2 = (const float*)d_in[6];
    const float* rw1 = (const float*)d_in[7];
    const float* rb1 = (const float*)d_in[8];
    const float* rw2 = (const float*)d_in[9];
    const float* rb2 = (const float*)d_in[10];
    float* out = (float*)d_out;

    __half *xp, *w1s, *w2s, *w1r, *w2r, *Hs, *Hr;
    cudaGetSymbolAddress((void**)&xp,  g_x);
    cudaGetSymbolAddress((void**)&w1s, g_w1s); cudaGetSymbolAddress((void**)&w2s, g_w2s);
    cudaGetSymbolAddress((void**)&w1r, g_w1r); cudaGetSymbolAddress((void**)&w2r, g_w2r);
    cudaGetSymbolAddress((void**)&Hs,  g_Hs);  cudaGetSymbolAddress((void**)&Hr,  g_Hr);

    static int smem_set = 0;
    if (!smem_set) {
        cudaFuncSetAttribute(k_mma<MF1S>, cudaFuncAttributeMaxDynamicSharedMemorySize, DSMEM_B);
        cudaFuncSetAttribute(k_mma<MF1R>, cudaFuncAttributeMaxDynamicSharedMemorySize, DSMEM_B);
        cudaFuncSetAttribute(k_mma<MF2S>, cudaFuncAttributeMaxDynamicSharedMemorySize, DSMEM_B);
        cudaFuncSetAttribute(k_mma<MF2R>, cudaFuncAttributeMaxDynamicSharedMemorySize, DSMEM_B);
        smem_set = 1;
    }

    k_init<<<(ROWS_CAP + 255) / 256, 256>>>();
    {
        int n4;
        n4 = (T_TOK * D_DIM) / 4;
        k_cvt1<<<(n4 + 255) / 256, 256>>>((const float4*)x, (__half2*)xp, n4);
        n4 = (NS_SH * F_DIM * D_DIM) / 4;
        k_cvt1<<<(n4 + 255) / 256, 256>>>((const float4*)sw1, (__half2*)w1s, n4);
        n4 = (NS_SH * D_DIM * F_DIM) / 4;
        k_cvt1<<<(n4 + 255) / 256, 256>>>((const float4*)sw2, (__half2*)w2s, n4);
        n4 = (E_EXP * F_DIM * D_DIM) / 4;
        k_cvt1<<<(n4 + 255) / 256, 256>>>((const float4*)rw1, (__half2*)w1r, n4);
        n4 = (E_EXP * D_DIM * F_DIM) / 4;
        k_cvt1<<<(n4 + 255) / 256, 256>>>((const float4*)rw2, (__half2*)w2r, n4);
    }

    k_router<<<T_TOK / 8, 256>>>(x, gw, gb);
    k_scan<<<1, 1>>>();
    k_assign<<<(T_TOK + 255) / 256, 256>>>();

    dim3 blk(256);
    // FFN1 shared: M=T, N=F, K=D
    k_mma<MF1S><<<dim3(F_DIM / BN, T_TOK / BM, NS_SH), blk, DSMEM_B>>>(xp, w1s, sb1, nullptr);
    // FFN1 routed: padded rows, N=F, K=D
    k_mma<MF1R><<<dim3(F_DIM / BN, T_TOK / BM, E_EXP), blk, DSMEM_B>>>(xp, w1r, rb1, nullptr);
    // FFN2 shared: M=T, N=D, K=NS*F
    k_mma<MF2S><<<dim3(D_DIM / BN, T_TOK / BM, 1),     blk, DSMEM_B>>>(Hs, w2s, sb2, out);
    // FFN2 routed: padded rows, N=D, K=F
    k_mma<MF2R><<<dim3(D_DIM / BN, T_TOK / BM, E_EXP), blk, DSMEM_B>>>(Hr, w2r, rb2, nullptr);
    // combine
    k_combine<<<(T_TOK * (D_DIM / 4) + 255) / 256, 256>>>(out);
}

// round 11
// speedup vs baseline: 11.4159x; 1.4760x over previous
#include <cuda_runtime.h>
#include <cuda_fp16.h>
#include <math.h>
#include <stdint.h>

// Problem constants
#define T_TOK 4096
#define D_DIM 512
#define F_DIM 2048
#define E_EXP 8
#define NS_SH 2
#define TOPK 2

// GEMM tiling
#define BM 128
#define BN 128
#define CK 64                         // K elems per chunk (128B fp16 rows)
#define STAGES 3
#define PLANE_B 16384                 // 128 rows * 128 B
#define STAGE_B (2*PLANE_B)           // A, B
#define DSMEM_B (STAGES*STAGE_B)      // 98304

#define ROWS_CAP (2*T_TOK + E_EXP*BM) // 9216 padded routed rows

// ---- device scratch (allocation-free rule: __device__ globals) ----
__device__ __align__(128) __half g_x  [T_TOK*D_DIM];
__device__ __align__(128) __half g_w1s[NS_SH*F_DIM*D_DIM];
__device__ __align__(128) __half g_w2s[NS_SH*D_DIM*F_DIM];
__device__ __align__(128) __half g_w1r[E_EXP*F_DIM*D_DIM];
__device__ __align__(128) __half g_w2r[E_EXP*D_DIM*F_DIM];
__device__ __align__(128) __half g_Hs [NS_SH*T_TOK*F_DIM];
__device__ __align__(128) __half g_Hr [ROWS_CAP*F_DIM];
__device__ __align__(128) float g_Or[ROWS_CAP*D_DIM];
__device__ __align__(128) float g_Os[T_TOK*D_DIM];      // shared FFN2 plane-1 partial
// routing state
__device__ int   g_counts[E_EXP];
__device__ int   g_poff[E_EXP + 1];
__device__ int   g_cursor[E_EXP];
__device__ int   g_ntiles[E_EXP];
__device__ int   g_eid[T_TOK * TOPK];
__device__ float g_wt[T_TOK * TOPK];
__device__ int   g_rows[T_TOK * TOPK];
__device__ int   g_row_token[ROWS_CAP];

__device__ __forceinline__ float gelu_exact(float v) {
    return 0.5f * v * (1.0f + erff(v * 0.70710678118654752440f));
}

// ================= PTX helpers =================
__device__ __forceinline__ uint32_t smem_u32(const void* p) {
    uint32_t a;
    asm("{ .reg .u64 t; cvta.to.shared.u64 t, %1; cvt.u32.u64 %0, t; }" : "=r"(a) : "l"(p));
    return a;
}
__device__ __forceinline__ void cp16(uint32_t s, const void* g) {
    asm volatile("cp.async.cg.shared.global [%0], [%1], 16;\n" :: "r"(s), "l"(g));
}
__device__ __forceinline__ void cp_commit() {
    asm volatile("cp.async.commit_group;\n" ::: "memory");
}
__device__ __forceinline__ void ldsm4(uint32_t& r0, uint32_t& r1, uint32_t& r2, uint32_t& r3,
                                      uint32_t addr) {
    asm volatile("ldmatrix.sync.aligned.m8n8.x4.shared.b16 {%0,%1,%2,%3}, [%4];"
                 : "=r"(r0), "=r"(r1), "=r"(r2), "=r"(r3) : "r"(addr));
}
__device__ __forceinline__ void mma_f16(float& c0, float& c1, float& c2, float& c3,
                                        uint32_t a0, uint32_t a1, uint32_t a2, uint32_t a3,
                                        uint32_t b0, uint32_t b1) {
    asm volatile(
        "mma.sync.aligned.m16n8k16.row.col.f32.f16.f16.f32 "
        "{%0,%1,%2,%3},{%4,%5,%6,%7},{%8,%9},{%0,%1,%2,%3};\n"
        : "+f"(c0), "+f"(c1), "+f"(c2), "+f"(c3)
        : "r"(a0), "r"(a1), "r"(a2), "r"(a3), "r"(b0), "r"(b1));
}

// ---- K0: reset per-call state ----
__global__ void k_init() {
    int i = blockIdx.x * blockDim.x + threadIdx.x;
    if (i < E_EXP) g_counts[i] = 0;
    if (i < ROWS_CAP) g_row_token[i] = 0;
}

// ---- fp32 -> fp16 round ----
__global__ void k_cvt1(const float4* __restrict__ s, __half2* __restrict__ h, int n4) {
    int i = blockIdx.x * blockDim.x + threadIdx.x;
    if (i >= n4) return;
    float4 v = s[i];
    h[2*i]   = __halves2half2(__float2half_rn(v.x), __float2half_rn(v.y));
    h[2*i+1] = __halves2half2(__float2half_rn(v.z), __float2half_rn(v.w));
}

// ---- K1: router (one warp per token) ----
__global__ void k_router(const float* __restrict__ x,
                         const float* __restrict__ gw,
                         const float* __restrict__ gb) {
    int warp = (blockIdx.x * blockDim.x + threadIdx.x) >> 5;
    int lane = threadIdx.x & 31;
    if (warp >= T_TOK) return;
    const float* xr = x + warp * D_DIM;
    float xv[16];
#pragma unroll
    for (int i = 0; i < 16; i++) xv[i] = xr[lane + 32 * i];
    float acc[E_EXP];
#pragma unroll
    for (int e = 0; e < E_EXP; e++) acc[e] = 0.f;
#pragma unroll
    for (int i = 0; i < 16; i++) {
        int d = lane + 32 * i;
#pragma unroll
        for (int e = 0; e < E_EXP; e++) acc[e] += xv[i] * gw[e * D_DIM + d];
    }
#pragma unroll
    for (int e = 0; e < E_EXP; e++) {
#pragma unroll
        for (int off = 16; off; off >>= 1)
            acc[e] += __shfl_xor_sync(0xffffffffu, acc[e], off);
    }
    if (lane == 0) {
        float lg[E_EXP], mx = -1e30f;
#pragma unroll
        for (int e = 0; e < E_EXP; e++) { lg[e] = acc[e] + gb[e]; mx = fmaxf(mx, lg[e]); }
        float s = 0.f;
#pragma unroll
        for (int e = 0; e < E_EXP; e++) { lg[e] = expf(lg[e] - mx); s += lg[e]; }
        float inv = 1.f / s;
#pragma unroll
        for (int e = 0; e < E_EXP; e++) lg[e] *= inv;
        int i1 = 0; float v1 = -1.f;
#pragma unroll
        for (int e = 0; e < E_EXP; e++) { if (lg[e] > v1) { v1 = lg[e]; i1 = e; } }
        int i2 = -1; float v2 = -1.f;
#pragma unroll
        for (int e = 0; e < E_EXP; e++) { if (e != i1 && lg[e] > v2) { v2 = lg[e]; i2 = e; } }
        g_eid[warp * 2 + 0] = i1;  g_wt[warp * 2 + 0] = v1;
        g_eid[warp * 2 + 1] = i2;  g_wt[warp * 2 + 1] = v2;
        atomicAdd(&g_counts[i1], 1);
        atomicAdd(&g_counts[i2], 1);
    }
}

// ---- K2: scan -> padded segments ----
__global__ void k_scan() {
    int off = 0;
    for (int e = 0; e < E_EXP; e++) {
        g_poff[e] = off;
        g_cursor[e] = off;
        int nt = (g_counts[e] + BM - 1) / BM;
        g_ntiles[e] = nt;
        off += nt * BM;
    }
    g_poff[E_EXP] = off;
}

// ---- K3: assign rows ----
__global__ void k_assign() {
    int t = blockIdx.x * blockDim.x + threadIdx.x;
    if (t >= T_TOK) return;
#pragma unroll
    for (int k = 0; k < TOPK; k++) {
        int e = g_eid[t * 2 + k];
        int r = atomicAdd(&g_cursor[e], 1);
        g_rows[t * 2 + k] = r;
        g_row_token[r] = t;
    }
}

// ==================== mma.sync GEMM (single fp16, fragment double-buffered) ====================
// C[M,N] = A[M,K] * B[N,K]^T, K-contiguous operands, fp32 accumulate.
// MF2S: z selects NS plane; z=0 writes out(+both biases), z=1 writes g_Os (no bias).
enum { MF1S = 0, MF1R = 1, MF2S = 2, MF2R = 3 };

template<int MODE>
__global__ void __launch_bounds__(256, 2) k_mma(
    const __half* __restrict__ Ap, const __half* __restrict__ Bp,
    const float* __restrict__ bias, float* __restrict__ outF) {
    int z = blockIdx.z;
    int row0;
    if (MODE == MF1R || MODE == MF2R) {
        if ((int)blockIdx.y >= g_ntiles[z]) return;
        row0 = g_poff[z] + blockIdx.y * BM;
    } else {
        row0 = blockIdx.y * BM;
    }
    int col0 = blockIdx.x * BN;

    const int KA = (MODE == MF1S || MODE == MF1R) ? D_DIM : F_DIM;
    const int NK = KA / CK;

    const __half *A0 = Ap, *B0 = Bp;
    if (MODE == MF1S || MODE == MF1R) B0 += (size_t)z * F_DIM * D_DIM;
    if (MODE == MF2R)                 B0 += (size_t)z * D_DIM * F_DIM;
    if (MODE == MF2S) {
        A0 += (size_t)z * T_TOK * F_DIM;
        B0 += (size_t)z * D_DIM * F_DIM;
    }

    extern __shared__ __align__(128) char dsm[];
    __shared__ int s_tok[BM];
    uint32_t sbase = smem_u32(dsm);

    int tid = threadIdx.x, wid = tid >> 5, lane = tid & 31;

    if (MODE == MF1R) {
        for (int i = tid; i < BM; i += 256) s_tok[i] = g_row_token[row0 + i];
        __syncthreads();
    }

    auto load_chunk = [&](int ci) {
        uint32_t sb = sbase + (ci % STAGES) * STAGE_B;
        int kk = ci * CK;
#pragma unroll
        for (int j = 0; j < 4; j++) {
            int idx = tid + j * 256;            // 0..1023
            int r = idx >> 3, u = idx & 7;
            uint32_t so = r * 128 + ((u ^ (r & 7)) * 16);
            int ar = (MODE == MF1R) ? s_tok[r] : (row0 + r);
            cp16(sb + so,           A0 + (size_t)ar * KA + kk + u * 8);
            cp16(sb + PLANE_B + so, B0 + (size_t)(col0 + r) * KA + kk + u * 8);
        }
        cp_commit();
    };

    // warp layout: 2x4 grid of 64x32 warp tiles
    int wr = (wid >> 2) * 64, wc = (wid & 3) * 32;
    int grp = lane >> 2, qp = lane & 3;
    int rl = lane & 15, hi = lane >> 4;

    float c[4][4][4];
#pragma unroll
    for (int i = 0; i < 4; i++)
#pragma unroll
        for (int j = 0; j < 4; j++)
#pragma unroll
            for (int q = 0; q < 4; q++) c[i][j][q] = 0.f;

    int npre = NK < STAGES ? NK : STAGES;
    for (int ci = 0; ci < npre; ci++) load_chunk(ci);

    uint32_t ah[2][4][4], bq[2][4][2];     // double-buffered fragments

    auto ld_frags = [&](uint32_t sb, int ks, int pb) {
        int cch = 2 * ks + hi;
#pragma unroll
        for (int mt = 0; mt < 4; mt++) {
            int r = wr + mt * 16 + rl;
            uint32_t ad = sb + r * 128 + ((cch ^ (r & 7)) << 4);
            ldsm4(ah[pb][mt][0], ah[pb][mt][1], ah[pb][mt][2], ah[pb][mt][3], ad);
        }
#pragma unroll
        for (int p = 0; p < 2; p++) {
            int r = wc + p * 16 + rl;
            uint32_t ad = sb + PLANE_B + r * 128 + ((cch ^ (r & 7)) << 4);
            uint32_t q0, q1, q2, q3;
            ldsm4(q0, q1, q2, q3, ad);
            bq[pb][2*p][0] = q0; bq[pb][2*p+1][0] = q1;
            bq[pb][2*p][1] = q2; bq[pb][2*p+1][1] = q3;
        }
    };

    for (int i = 0; i < NK; i++) {
        int issued = (NK < i + STAGES) ? NK : (i + STAGES);
        int pend = issued - i - 1;
        if (pend >= 2)      asm volatile("cp.async.wait_group 2;" ::: "memory");
        else if (pend == 1) asm volatile("cp.async.wait_group 1;" ::: "memory");
        else                asm volatile("cp.async.wait_group 0;" ::: "memory");
        __syncthreads();
        uint32_t sb = sbase + (i % STAGES) * STAGE_B;

        ld_frags(sb, 0, 0);
#pragma unroll
        for (int ks = 0; ks < 4; ks++) {
            int cur = ks & 1;
            if (ks < 3) ld_frags(sb, ks + 1, cur ^ 1);
#pragma unroll
            for (int mt = 0; mt < 4; mt++)
#pragma unroll
                for (int nt = 0; nt < 4; nt++)
                    mma_f16(c[mt][nt][0], c[mt][nt][1], c[mt][nt][2], c[mt][nt][3],
                            ah[cur][mt][0], ah[cur][mt][1], ah[cur][mt][2], ah[cur][mt][3],
                            bq[cur][nt][0], bq[cur][nt][1]);
        }
        __syncthreads();
        if (i + STAGES < NK) load_chunk(i + STAGES);
    }

    // ---- epilogue ----
#pragma unroll
    for (int mt = 0; mt < 4; ++mt) {
        int r = row0 + wr + mt * 16 + grp;
#pragma unroll
        for (int nt = 0; nt < 4; ++nt) {
            int cg = col0 + wc + nt * 8 + qp * 2;
            float c0 = c[mt][nt][0], c1 = c[mt][nt][1];
            float c2 = c[mt][nt][2], c3 = c[mt][nt][3];
            if (MODE == MF1S || MODE == MF1R) {
                const float* bz = bias + (size_t)z * F_DIM;
                float b0 = bz[cg], b1 = bz[cg + 1];
                float h0 = gelu_exact(c0 + b0), h1 = gelu_exact(c1 + b1);
                float h2 = gelu_exact(c2 + b0), h3 = gelu_exact(c3 + b1);
                __half* Hh = (MODE == MF1S) ? (g_Hs + (size_t)z * T_TOK * F_DIM) : g_Hr;
                *(__half2*)(Hh + (size_t)r * F_DIM + cg) =
                    __halves2half2(__float2half_rn(h0), __float2half_rn(h1));
                *(__half2*)(Hh + (size_t)(r + 8) * F_DIM + cg) =
                    __halves2half2(__float2half_rn(h2), __float2half_rn(h3));
            } else if (MODE == MF2S) {
                if (z == 0) {
                    float b0 = bias[cg] + bias[D_DIM + cg];
                    float b1 = bias[cg + 1] + bias[D_DIM + cg + 1];
                    float2 v;
                    v.x = c0 + b0; v.y = c1 + b1;
                    *(float2*)&outF[(size_t)r * D_DIM + cg] = v;
                    v.x = c2 + b0; v.y = c3 + b1;
                    *(float2*)&outF[(size_t)(r + 8) * D_DIM + cg] = v;
                } else {
                    float2 v;
                    v.x = c0; v.y = c1;
                    *(float2*)&g_Os[(size_t)r * D_DIM + cg] = v;
                    v.x = c2; v.y = c3;
                    *(float2*)&g_Os[(size_t)(r + 8) * D_DIM + cg] = v;
                }
            } else {  // MF2R
                const float* bz = bias + (size_t)z * D_DIM;
                float b0 = bz[cg], b1 = bz[cg + 1];
                float2 v;
                v.x = c0 + b0; v.y = c1 + b1;
                *(float2*)&g_Or[(size_t)r * D_DIM + cg] = v;
                v.x = c2 + b0; v.y = c3 + b1;
                *(float2*)&g_Or[(size_t)(r + 8) * D_DIM + cg] = v;
            }
        }
    }
}

// ---- combine: out += shared plane-1 partial + weighted routed ----
__global__ void k_combine(float* __restrict__ out) {
    int idx = blockIdx.x * blockDim.x + threadIdx.x;
    if (idx >= T_TOK * (D_DIM / 4)) return;
    int t = idx >> 7;
    int dq = idx & 127;
    float4 o = ((float4*)out)[t * 128 + dq];
    float4 s = ((const float4*)g_Os)[t * 128 + dq];
    int r0 = g_rows[t * 2 + 0], r1 = g_rows[t * 2 + 1];
    float w0 = g_wt[t * 2 + 0], w1 = g_wt[t * 2 + 1];
    float4 a = ((const float4*)g_Or)[(size_t)r0 * 128 + dq];
    float4 b = ((const float4*)g_Or)[(size_t)r1 * 128 + dq];
    o.x += s.x + w0 * a.x + w1 * b.x;
    o.y += s.y + w0 * a.y + w1 * b.y;
    o.z += s.z + w0 * a.z + w1 * b.z;
    o.w += s.w + w0 * a.w + w1 * b.w;
    ((float4*)out)[t * 128 + dq] = o;
}

extern "C" void kernel_launch(void* const* d_in, const int* in_sizes, int n_in,
                              void* d_out, int out_size) {
    const float* x   = (const float*)d_in[0];
    const float* gw  = (const float*)d_in[1];
    const float* gb  = (const float*)d_in[2];
    const float* sw1 = (const float*)d_in[3];
    const float* sb1 = (const float*)d_in[4];
    const float* sw2 = (const float*)d_in[5];
    const float* sb2 = (const float*)d_in[6];
    const float* rw1 = (const float*)d_in[7];
    const float* rb1 = (const float*)d_in[8];
    const float* rw2 = (const float*)d_in[9];
    const float* rb2 = (const float*)d_in[10];
    float* out = (float*)d_out;

    __half *xp, *w1s, *w2s, *w1r, *w2r, *Hs, *Hr;
    cudaGetSymbolAddress((void**)&xp,  g_x);
    cudaGetSymbolAddress((void**)&w1s, g_w1s); cudaGetSymbolAddress((void**)&w2s, g_w2s);
    cudaGetSymbolAddress((void**)&w1r, g_w1r); cudaGetSymbolAddress((void**)&w2r, g_w2r);
    cudaGetSymbolAddress((void**)&Hs,  g_Hs);  cudaGetSymbolAddress((void**)&Hr,  g_Hr);

    static int smem_set = 0;
    if (!smem_set) {
        cudaFuncSetAttribute(k_mma<MF1S>, cudaFuncAttributeMaxDynamicSharedMemorySize, DSMEM_B);
        cudaFuncSetAttribute(k_mma<MF1R>, cudaFuncAttributeMaxDynamicSharedMemorySize, DSMEM_B);
        cudaFuncSetAttribute(k_mma<MF2S>, cudaFuncAttributeMaxDynamicSharedMemorySize, DSMEM_B);
        cudaFuncSetAttribute(k_mma<MF2R>, cudaFuncAttributeMaxDynamicSharedMemorySize, DSMEM_B);
        smem_set = 1;
    }

    k_init<<<(ROWS_CAP + 255) / 256, 256>>>();
    {
        int n4;
        n4 = (T_TOK * D_DIM) / 4;
        k_cvt1<<<(n4 + 255) / 256, 256>>>((const float4*)x, (__half2*)xp, n4);
        n4 = (NS_SH * F_DIM * D_DIM) / 4;
        k_cvt1<<<(n4 + 255) / 256, 256>>>((const float4*)sw1, (__half2*)w1s, n4);
        n4 = (NS_SH * D_DIM * F_DIM) / 4;
        k_cvt1<<<(n4 + 255) / 256, 256>>>((const float4*)sw2, (__half2*)w2s, n4);
        n4 = (E_EXP * F_DIM * D_DIM) / 4;
        k_cvt1<<<(n4 + 255) / 256, 256>>>((const float4*)rw1, (__half2*)w1r, n4);
        n4 = (E_EXP * D_DIM * F_DIM) / 4;
        k_cvt1<<<(n4 + 255) / 256, 256>>>((const float4*)rw2, (__half2*)w2r, n4);
    }

    k_router<<<T_TOK / 8, 256>>>(x, gw, gb);
    k_scan<<<1, 1>>>();
    k_assign<<<(T_TOK + 255) / 256, 256>>>();

    dim3 blk(256);
    // FFN1 shared: M=T, N=F, K=D
    k_mma<MF1S><<<dim3(F_DIM / BN, T_TOK / BM, NS_SH), blk, DSMEM_B>>>(xp, w1s, sb1, nullptr);
    // FFN1 routed: padded rows, N=F, K=D
    k_mma<MF1R><<<dim3(F_DIM / BN, T_TOK / BM, E_EXP), blk, DSMEM_B>>>(xp, w1r, rb1, nullptr);
    // FFN2 shared: M=T, N=D, K=F per plane; z=0 -> out(+bias), z=1 -> g_Os
    k_mma<MF2S><<<dim3(D_DIM / BN, T_TOK / BM, NS_SH), blk, DSMEM_B>>>(Hs, w2s, sb2, out);
    // FFN2 routed: padded rows, N=D, K=F
    k_mma<MF2R><<<dim3(D_DIM / BN, T_TOK / BM, E_EXP), blk, DSMEM_B>>>(Hr, w2r, rb2, nullptr);
    // combine
    k_combine<<<(T_TOK * (D_DIM / 4) + 255) / 256, 256>>>(out);
}

// round 12
// speedup vs baseline: 11.7686x; 1.0309x over previous
#include <cuda_runtime.h>
#include <cuda_fp16.h>
#include <math.h>
#include <stdint.h>

// Problem constants
#define T_TOK 4096
#define D_DIM 512
#define F_DIM 2048
#define E_EXP 8
#define NS_SH 2
#define TOPK 2

// GEMM tiling
#define BM 128
#define BN 128
#define CK 64                         // K elems per chunk (128B fp16 rows)
#define STAGES 3
#define PLANE_B 16384                 // 128 rows * 128 B
#define STAGE_B (2*PLANE_B)           // A, B
#define DSMEM_B (STAGES*STAGE_B)      // 98304

#define ROWS_CAP (2*T_TOK + E_EXP*BM) // 9216 padded routed rows

// conversion region sizes (in float4 units)
#define N4_X   ((T_TOK*D_DIM)/4)             // 524288
#define N4_W1S ((NS_SH*F_DIM*D_DIM)/4)       // 524288
#define N4_W2S ((NS_SH*D_DIM*F_DIM)/4)       // 524288
#define N4_W1R ((E_EXP*F_DIM*D_DIM)/4)       // 2097152
#define N4_W2R ((E_EXP*D_DIM*F_DIM)/4)       // 2097152
#define N4_TOT (N4_X+N4_W1S+N4_W2S+N4_W1R+N4_W2R)

// ---- device scratch (allocation-free rule: __device__ globals) ----
__device__ __align__(128) __half g_x  [T_TOK*D_DIM];
__device__ __align__(128) __half g_w1s[NS_SH*F_DIM*D_DIM];
__device__ __align__(128) __half g_w2s[NS_SH*D_DIM*F_DIM];
__device__ __align__(128) __half g_w1r[E_EXP*F_DIM*D_DIM];
__device__ __align__(128) __half g_w2r[E_EXP*D_DIM*F_DIM];
__device__ __align__(128) __half g_Hs [NS_SH*T_TOK*F_DIM];
__device__ __align__(128) __half g_Hr [ROWS_CAP*F_DIM];
__device__ __align__(128) float g_Or[ROWS_CAP*D_DIM];
__device__ __align__(128) float g_Os[T_TOK*D_DIM];      // shared FFN2 plane-1 partial
// routing state
__device__ int   g_counts[E_EXP];
__device__ int   g_poff[E_EXP + 1];
__device__ int   g_cursor[E_EXP];
__device__ int   g_ntiles[E_EXP];
__device__ int   g_eid[T_TOK * TOPK];
__device__ float g_wt[T_TOK * TOPK];
__device__ int   g_rows[T_TOK * TOPK];
__device__ int   g_row_token[ROWS_CAP];

__device__ __forceinline__ float gelu_exact(float v) {
    return 0.5f * v * (1.0f + erff(v * 0.70710678118654752440f));
}

// ================= PTX helpers =================
__device__ __forceinline__ uint32_t smem_u32(const void* p) {
    uint32_t a;
    asm("{ .reg .u64 t; cvta.to.shared.u64 t, %1; cvt.u32.u64 %0, t; }" : "=r"(a) : "l"(p));
    return a;
}
__device__ __forceinline__ void cp16(uint32_t s, const void* g) {
    asm volatile("cp.async.cg.shared.global [%0], [%1], 16;\n" :: "r"(s), "l"(g));
}
__device__ __forceinline__ void cp_commit() {
    asm volatile("cp.async.commit_group;\n" ::: "memory");
}
__device__ __forceinline__ void ldsm4(uint32_t& r0, uint32_t& r1, uint32_t& r2, uint32_t& r3,
                                      uint32_t addr) {
    asm volatile("ldmatrix.sync.aligned.m8n8.x4.shared.b16 {%0,%1,%2,%3}, [%4];"
                 : "=r"(r0), "=r"(r1), "=r"(r2), "=r"(r3) : "r"(addr));
}
__device__ __forceinline__ void mma_f16(float& c0, float& c1, float& c2, float& c3,
                                        uint32_t a0, uint32_t a1, uint32_t a2, uint32_t a3,
                                        uint32_t b0, uint32_t b1) {
    asm volatile(
        "mma.sync.aligned.m16n8k16.row.col.f32.f16.f16.f32 "
        "{%0,%1,%2,%3},{%4,%5,%6,%7},{%8,%9},{%0,%1,%2,%3};\n"
        : "+f"(c0), "+f"(c1), "+f"(c2), "+f"(c3)
        : "r"(a0), "r"(a1), "r"(a2), "r"(a3), "r"(b0), "r"(b1));
}

// ---- fused: fp32 -> fp16 for all 5 tensors + per-call state reset ----
__global__ void k_cvt_all(const float4* __restrict__ x,   const float4* __restrict__ sw1,
                          const float4* __restrict__ sw2, const float4* __restrict__ rw1,
                          const float4* __restrict__ rw2) {
    int gi = blockIdx.x * blockDim.x + threadIdx.x;
    // state reset piggyback
    if (gi < E_EXP) g_counts[gi] = 0;
    if (gi < ROWS_CAP) g_row_token[gi] = 0;

    for (int i = gi; i < N4_TOT; i += gridDim.x * blockDim.x) {
        const float4* src;
        __half2* dst;
        int j = i;
        if (j < N4_X)                  { src = x;   dst = (__half2*)g_x; }
        else if ((j -= N4_X)   < N4_W1S) { src = sw1; dst = (__half2*)g_w1s; }
        else if ((j -= N4_W1S) < N4_W2S) { src = sw2; dst = (__half2*)g_w2s; }
        else if ((j -= N4_W2S) < N4_W1R) { src = rw1; dst = (__half2*)g_w1r; }
        else { j -= N4_W1R;              src = rw2; dst = (__half2*)g_w2r; }
        float4 v = src[j];
        dst[2*j]   = __halves2half2(__float2half_rn(v.x), __float2half_rn(v.y));
        dst[2*j+1] = __halves2half2(__float2half_rn(v.z), __float2half_rn(v.w));
    }
}

// ---- K1: router (one warp per token) ----
__global__ void k_router(const float* __restrict__ x,
                         const float* __restrict__ gw,
                         const float* __restrict__ gb) {
    int warp = (blockIdx.x * blockDim.x + threadIdx.x) >> 5;
    int lane = threadIdx.x & 31;
    if (warp >= T_TOK) return;
    const float* xr = x + warp * D_DIM;
    float xv[16];
#pragma unroll
    for (int i = 0; i < 16; i++) xv[i] = xr[lane + 32 * i];
    float acc[E_EXP];
#pragma unroll
    for (int e = 0; e < E_EXP; e++) acc[e] = 0.f;
#pragma unroll
    for (int i = 0; i < 16; i++) {
        int d = lane + 32 * i;
#pragma unroll
        for (int e = 0; e < E_EXP; e++) acc[e] += xv[i] * gw[e * D_DIM + d];
    }
#pragma unroll
    for (int e = 0; e < E_EXP; e++) {
#pragma unroll
        for (int off = 16; off; off >>= 1)
            acc[e] += __shfl_xor_sync(0xffffffffu, acc[e], off);
    }
    if (lane == 0) {
        float lg[E_EXP], mx = -1e30f;
#pragma unroll
        for (int e = 0; e < E_EXP; e++) { lg[e] = acc[e] + gb[e]; mx = fmaxf(mx, lg[e]); }
        float s = 0.f;
#pragma unroll
        for (int e = 0; e < E_EXP; e++) { lg[e] = expf(lg[e] - mx); s += lg[e]; }
        float inv = 1.f / s;
#pragma unroll
        for (int e = 0; e < E_EXP; e++) lg[e] *= inv;
        int i1 = 0; float v1 = -1.f;
#pragma unroll
        for (int e = 0; e < E_EXP; e++) { if (lg[e] > v1) { v1 = lg[e]; i1 = e; } }
        int i2 = -1; float v2 = -1.f;
#pragma unroll
        for (int e = 0; e < E_EXP; e++) { if (e != i1 && lg[e] > v2) { v2 = lg[e]; i2 = e; } }
        g_eid[warp * 2 + 0] = i1;  g_wt[warp * 2 + 0] = v1;
        g_eid[warp * 2 + 1] = i2;  g_wt[warp * 2 + 1] = v2;
        atomicAdd(&g_counts[i1], 1);
        atomicAdd(&g_counts[i2], 1);
    }
}

// ---- K2: scan -> padded segments ----
__global__ void k_scan() {
    int off = 0;
    for (int e = 0; e < E_EXP; e++) {
        g_poff[e] = off;
        g_cursor[e] = off;
        int nt = (g_counts[e] + BM - 1) / BM;
        g_ntiles[e] = nt;
        off += nt * BM;
    }
    g_poff[E_EXP] = off;
}

// ---- K3: assign rows ----
__global__ void k_assign() {
    int t = blockIdx.x * blockDim.x + threadIdx.x;
    if (t >= T_TOK) return;
#pragma unroll
    for (int k = 0; k < TOPK; k++) {
        int e = g_eid[t * 2 + k];
        int r = atomicAdd(&g_cursor[e], 1);
        g_rows[t * 2 + k] = r;
        g_row_token[r] = t;
    }
}

// ==================== mma.sync GEMM (single fp16, fragment double-buffered) ====================
// C[M,N] = A[M,K] * B[N,K]^T, K-contiguous operands, fp32 accumulate.
// MF2S: z selects NS plane; z=0 writes out(+both biases), z=1 writes g_Os (no bias).
enum { MF1S = 0, MF1R = 1, MF2S = 2, MF2R = 3 };

template<int MODE>
__global__ void __launch_bounds__(256, 2) k_mma(
    const __half* __restrict__ Ap, const __half* __restrict__ Bp,
    const float* __restrict__ bias, float* __restrict__ outF) {
    int z = blockIdx.z;
    int row0;
    if (MODE == MF1R || MODE == MF2R) {
        if ((int)blockIdx.y >= g_ntiles[z]) return;
        row0 = g_poff[z] + blockIdx.y * BM;
    } else {
        row0 = blockIdx.y * BM;
    }
    int col0 = blockIdx.x * BN;

    const int KA = (MODE == MF1S || MODE == MF1R) ? D_DIM : F_DIM;
    const int NK = KA / CK;

    const __half *A0 = Ap, *B0 = Bp;
    if (MODE == MF1S || MODE == MF1R) B0 += (size_t)z * F_DIM * D_DIM;
    if (MODE == MF2R)                 B0 += (size_t)z * D_DIM * F_DIM;
    if (MODE == MF2S) {
        A0 += (size_t)z * T_TOK * F_DIM;
        B0 += (size_t)z * D_DIM * F_DIM;
    }

    extern __shared__ __align__(128) char dsm[];
    __shared__ int s_tok[BM];
    uint32_t sbase = smem_u32(dsm);

    int tid = threadIdx.x, wid = tid >> 5, lane = tid & 31;

    if (MODE == MF1R) {
        for (int i = tid; i < BM; i += 256) s_tok[i] = g_row_token[row0 + i];
        __syncthreads();
    }

    auto load_chunk = [&](int ci) {
        uint32_t sb = sbase + (ci % STAGES) * STAGE_B;
        int kk = ci * CK;
#pragma unroll
        for (int j = 0; j < 4; j++) {
            int idx = tid + j * 256;            // 0..1023
            int r = idx >> 3, u = idx & 7;
            uint32_t so = r * 128 + ((u ^ (r & 7)) * 16);
            int ar = (MODE == MF1R) ? s_tok[r] : (row0 + r);
            cp16(sb + so,           A0 + (size_t)ar * KA + kk + u * 8);
            cp16(sb + PLANE_B + so, B0 + (size_t)(col0 + r) * KA + kk + u * 8);
        }
        cp_commit();
    };

    // warp layout: 2x4 grid of 64x32 warp tiles
    int wr = (wid >> 2) * 64, wc = (wid & 3) * 32;
    int grp = lane >> 2, qp = lane & 3;
    int rl = lane & 15, hi = lane >> 4;

    float c[4][4][4];
#pragma unroll
    for (int i = 0; i < 4; i++)
#pragma unroll
        for (int j = 0; j < 4; j++)
#pragma unroll
            for (int q = 0; q < 4; q++) c[i][j][q] = 0.f;

    int npre = NK < STAGES ? NK : STAGES;
    for (int ci = 0; ci < npre; ci++) load_chunk(ci);

    uint32_t ah[2][4][4], bq[2][4][2];     // double-buffered fragments

    auto ld_frags = [&](uint32_t sb, int ks, int pb) {
        int cch = 2 * ks + hi;
#pragma unroll
        for (int mt = 0; mt < 4; mt++) {
            int r = wr + mt * 16 + rl;
            uint32_t ad = sb + r * 128 + ((cch ^ (r & 7)) << 4);
            ldsm4(ah[pb][mt][0], ah[pb][mt][1], ah[pb][mt][2], ah[pb][mt][3], ad);
        }
#pragma unroll
        for (int p = 0; p < 2; p++) {
            int r = wc + p * 16 + rl;
            uint32_t ad = sb + PLANE_B + r * 128 + ((cch ^ (r & 7)) << 4);
            uint32_t q0, q1, q2, q3;
            ldsm4(q0, q1, q2, q3, ad);
            bq[pb][2*p][0] = q0; bq[pb][2*p+1][0] = q1;
            bq[pb][2*p][1] = q2; bq[pb][2*p+1][1] = q3;
        }
    };

    for (int i = 0; i < NK; i++) {
        int issued = (NK < i + STAGES) ? NK : (i + STAGES);
        int pend = issued - i - 1;
        if (pend >= 2)      asm volatile("cp.async.wait_group 2;" ::: "memory");
        else if (pend == 1) asm volatile("cp.async.wait_group 1;" ::: "memory");
        else                asm volatile("cp.async.wait_group 0;" ::: "memory");
        __syncthreads();
        uint32_t sb = sbase + (i % STAGES) * STAGE_B;

        ld_frags(sb, 0, 0);
#pragma unroll
        for (int ks = 0; ks < 4; ks++) {
            int cur = ks & 1;
            if (ks < 3) ld_frags(sb, ks + 1, cur ^ 1);
#pragma unroll
            for (int mt = 0; mt < 4; mt++)
#pragma unroll
                for (int nt = 0; nt < 4; nt++)
                    mma_f16(c[mt][nt][0], c[mt][nt][1], c[mt][nt][2], c[mt][nt][3],
                            ah[cur][mt][0], ah[cur][mt][1], ah[cur][mt][2], ah[cur][mt][3],
                            bq[cur][nt][0], bq[cur][nt][1]);
        }
        __syncthreads();
        if (i + STAGES < NK) load_chunk(i + STAGES);
    }

    // ---- epilogue ----
#pragma unroll
    for (int mt = 0; mt < 4; ++mt) {
        int r = row0 + wr + mt * 16 + grp;
#pragma unroll
        for (int nt = 0; nt < 4; ++nt) {
            int cg = col0 + wc + nt * 8 + qp * 2;
            float c0 = c[mt][nt][0], c1 = c[mt][nt][1];
            float c2 = c[mt][nt][2], c3 = c[mt][nt][3];
            if (MODE == MF1S || MODE == MF1R) {
                const float* bz = bias + (size_t)z * F_DIM;
                float b0 = bz[cg], b1 = bz[cg + 1];
                float h0 = gelu_exact(c0 + b0), h1 = gelu_exact(c1 + b1);
                float h2 = gelu_exact(c2 + b0), h3 = gelu_exact(c3 + b1);
                __half* Hh = (MODE == MF1S) ? (g_Hs + (size_t)z * T_TOK * F_DIM) : g_Hr;
                *(__half2*)(Hh + (size_t)r * F_DIM + cg) =
                    __halves2half2(__float2half_rn(h0), __float2half_rn(h1));
                *(__half2*)(Hh + (size_t)(r + 8) * F_DIM + cg) =
                    __halves2half2(__float2half_rn(h2), __float2half_rn(h3));
            } else if (MODE == MF2S) {
                if (z == 0) {
                    float b0 = bias[cg] + bias[D_DIM + cg];
                    float b1 = bias[cg + 1] + bias[D_DIM + cg + 1];
                    float2 v;
                    v.x = c0 + b0; v.y = c1 + b1;
                    *(float2*)&outF[(size_t)r * D_DIM + cg] = v;
                    v.x = c2 + b0; v.y = c3 + b1;
                    *(float2*)&outF[(size_t)(r + 8) * D_DIM + cg] = v;
                } else {
                    float2 v;
                    v.x = c0; v.y = c1;
                    *(float2*)&g_Os[(size_t)r * D_DIM + cg] = v;
                    v.x = c2; v.y = c3;
                    *(float2*)&g_Os[(size_t)(r + 8) * D_DIM + cg] = v;
                }
            } else {  // MF2R
                const float* bz = bias + (size_t)z * D_DIM;
                float b0 = bz[cg], b1 = bz[cg + 1];
                float2 v;
                v.x = c0 + b0; v.y = c1 + b1;
                *(float2*)&g_Or[(size_t)r * D_DIM + cg] = v;
                v.x = c2 + b0; v.y = c3 + b1;
                *(float2*)&g_Or[(size_t)(r + 8) * D_DIM + cg] = v;
            }
        }
    }
}

// ---- combine: out += shared plane-1 partial + weighted routed ----
__global__ void k_combine(float* __restrict__ out) {
    int idx = blockIdx.x * blockDim.x + threadIdx.x;
    if (idx >= T_TOK * (D_DIM / 4)) return;
    int t = idx >> 7;
    int dq = idx & 127;
    float4 o = ((float4*)out)[t * 128 + dq];
    float4 s = ((const float4*)g_Os)[t * 128 + dq];
    int r0 = g_rows[t * 2 + 0], r1 = g_rows[t * 2 + 1];
    float w0 = g_wt[t * 2 + 0], w1 = g_wt[t * 2 + 1];
    float4 a = ((const float4*)g_Or)[(size_t)r0 * 128 + dq];
    float4 b = ((const float4*)g_Or)[(size_t)r1 * 128 + dq];
    o.x += s.x + w0 * a.x + w1 * b.x;
    o.y += s.y + w0 * a.y + w1 * b.y;
    o.z += s.z + w0 * a.z + w1 * b.z;
    o.w += s.w + w0 * a.w + w1 * b.w;
    ((float4*)out)[t * 128 + dq] = o;
}

extern "C" void kernel_launch(void* const* d_in, const int* in_sizes, int n_in,
                              void* d_out, int out_size) {
    const float* x   = (const float*)d_in[0];
    const float* gw  = (const float*)d_in[1];
    const float* gb  = (const float*)d_in[2];
    const float* sw1 = (const float*)d_in[3];
    const float* sb1 = (const float*)d_in[4];
    const float* sw2 = (const float*)d_in[5];
    const float* sb2 = (const float*)d_in[6];
    const float* rw1 = (const float*)d_in[7];
    const float* rb1 = (const float*)d_in[8];
    const float* rw2 = (const float*)d_in[9];
    const float* rb2 = (const float*)d_in[10];
    float* out = (float*)d_out;

    __half *xp, *w1s, *w2s, *w1r, *w2r, *Hs, *Hr;
    cudaGetSymbolAddress((void**)&xp,  g_x);
    cudaGetSymbolAddress((void**)&w1s, g_w1s); cudaGetSymbolAddress((void**)&w2s, g_w2s);
    cudaGetSymbolAddress((void**)&w1r, g_w1r); cudaGetSymbolAddress((void**)&w2r, g_w2r);
    cudaGetSymbolAddress((void**)&Hs,  g_Hs);  cudaGetSymbolAddress((void**)&Hr,  g_Hr);

    static int smem_set = 0;
    if (!smem_set) {
        cudaFuncSetAttribute(k_mma<MF1S>, cudaFuncAttributeMaxDynamicSharedMemorySize, DSMEM_B);
        cudaFuncSetAttribute(k_mma<MF1R>, cudaFuncAttributeMaxDynamicSharedMemorySize, DSMEM_B);
        cudaFuncSetAttribute(k_mma<MF2S>, cudaFuncAttributeMaxDynamicSharedMemorySize, DSMEM_B);
        cudaFuncSetAttribute(k_mma<MF2R>, cudaFuncAttributeMaxDynamicSharedMemorySize, DSMEM_B);
        smem_set = 1;
    }

    // fused conversion (all weights + x) + state reset; sized for ~4 items/thread
    k_cvt_all<<<5632, 256>>>((const float4*)x, (const float4*)sw1, (const float4*)sw2,
                             (const float4*)rw1, (const float4*)rw2);

    k_router<<<T_TOK / 8, 256>>>(x, gw, gb);
    k_scan<<<1, 1>>>();
    k_assign<<<(T_TOK + 255) / 256, 256>>>();

    dim3 blk(256);
    // FFN1 shared: M=T, N=F, K=D
    k_mma<MF1S><<<dim3(F_DIM / BN, T_TOK / BM, NS_SH), blk, DSMEM_B>>>(xp, w1s, sb1, nullptr);
    // FFN1 routed: padded rows, N=F, K=D
    k_mma<MF1R><<<dim3(F_DIM / BN, T_TOK / BM, E_EXP), blk, DSMEM_B>>>(xp, w1r, rb1, nullptr);
    // FFN2 shared: M=T, N=D, K=F per plane; z=0 -> out(+bias), z=1 -> g_Os
    k_mma<MF2S><<<dim3(D_DIM / BN, T_TOK / BM, NS_SH), blk, DSMEM_B>>>(Hs, w2s, sb2, out);
    // FFN2 routed: padded rows, N=D, K=F
    k_mma<MF2R><<<dim3(D_DIM / BN, T_TOK / BM, E_EXP), blk, DSMEM_B>>>(Hr, w2r, rb2, nullptr);
    // combine
    k_combine<<<(T_TOK * (D_DIM / 4) + 255) / 256, 256>>>(out);
}

// round 15
// speedup vs baseline: 12.4278x; 1.0560x over previous
#include <cuda_runtime.h>
#include <cuda_fp16.h>
#include <math.h>
#include <stdint.h>

// Problem constants
#define T_TOK 4096
#define D_DIM 512
#define F_DIM 2048
#define E_EXP 8
#define NS_SH 2
#define TOPK 2

// GEMM tiling
#define BM 128
#define BN 128
#define CK 64                         // K elems per chunk (128B fp16 rows)
#define STAGES 3
#define PLANE_B 16384                 // 128 rows * 128 B
#define STAGE_B (2*PLANE_B)           // A, B
#define DSMEM_B (STAGES*STAGE_B)      // 98304

#define ROWS_CAP (E_EXP*T_TOK)        // fixed per-expert segments (32768 rows)

// conversion region sizes (in float4 units)
#define N4_X   ((T_TOK*D_DIM)/4)
#define N4_W1S ((NS_SH*F_DIM*D_DIM)/4)
#define N4_W2S ((NS_SH*D_DIM*F_DIM)/4)
#define N4_W1R ((E_EXP*F_DIM*D_DIM)/4)
#define N4_W2R ((E_EXP*D_DIM*F_DIM)/4)
#define N4_TOT (N4_X+N4_W1S+N4_W2S+N4_W1R+N4_W2R)

// ---- device scratch (allocation-free rule: __device__ globals) ----
__device__ __align__(128) __half g_x  [T_TOK*D_DIM];
__device__ __align__(128) __half g_w1s[NS_SH*F_DIM*D_DIM];
__device__ __align__(128) __half g_w2s[NS_SH*D_DIM*F_DIM];
__device__ __align__(128) __half g_w1r[E_EXP*F_DIM*D_DIM];
__device__ __align__(128) __half g_w2r[E_EXP*D_DIM*F_DIM];
__device__ __align__(128) __half g_Hs [NS_SH*T_TOK*F_DIM];
__device__ __align__(128) __half g_Hr [(size_t)ROWS_CAP*F_DIM];   // 128 MB
__device__ __align__(128) float g_Or[(size_t)ROWS_CAP*D_DIM];     // 64 MB
__device__ __align__(128) float g_Os[T_TOK*D_DIM];                // shared FFN2 plane-1 partial
// routing state
__device__ int   g_cursor[E_EXP];
__device__ float g_wt[T_TOK * TOPK];
__device__ int   g_rows[T_TOK * TOPK];
__device__ int   g_row_token[ROWS_CAP];

__device__ __forceinline__ float gelu_exact(float v) {
    return 0.5f * v * (1.0f + erff(v * 0.70710678118654752440f));
}

// ================= PTX helpers =================
__device__ __forceinline__ uint32_t smem_u32(const void* p) {
    uint32_t a;
    asm("{ .reg .u64 t; cvta.to.shared.u64 t, %1; cvt.u32.u64 %0, t; }" : "=r"(a) : "l"(p));
    return a;
}
__device__ __forceinline__ void cp16(uint32_t s, const void* g) {
    asm volatile("cp.async.cg.shared.global [%0], [%1], 16;\n" :: "r"(s), "l"(g));
}
__device__ __forceinline__ void cp_commit() {
    asm volatile("cp.async.commit_group;\n" ::: "memory");
}
__device__ __forceinline__ void ldsm4(uint32_t& r0, uint32_t& r1, uint32_t& r2, uint32_t& r3,
                                      uint32_t addr) {
    asm volatile("ldmatrix.sync.aligned.m8n8.x4.shared.b16 {%0,%1,%2,%3}, [%4];"
                 : "=r"(r0), "=r"(r1), "=r"(r2), "=r"(r3) : "r"(addr));
}
__device__ __forceinline__ void mma_f16(float& c0, float& c1, float& c2, float& c3,
                                        uint32_t a0, uint32_t a1, uint32_t a2, uint32_t a3,
                                        uint32_t b0, uint32_t b1) {
    asm volatile(
        "mma.sync.aligned.m16n8k16.row.col.f32.f16.f16.f32 "
        "{%0,%1,%2,%3},{%4,%5,%6,%7},{%8,%9},{%0,%1,%2,%3};\n"
        : "+f"(c0), "+f"(c1), "+f"(c2), "+f"(c3)
        : "r"(a0), "r"(a1), "r"(a2), "r"(a3), "r"(b0), "r"(b1));
}

// ---- fused: fp32 -> fp16 for all 5 tensors + per-call state reset ----
__global__ void k_cvt_all(const float4* __restrict__ x,   const float4* __restrict__ sw1,
                          const float4* __restrict__ sw2, const float4* __restrict__ rw1,
                          const float4* __restrict__ rw2) {
    int gi = blockIdx.x * blockDim.x + threadIdx.x;
    if (gi < E_EXP) g_cursor[gi] = 0;
    if (gi < ROWS_CAP) g_row_token[gi] = 0;

    for (int i = gi; i < N4_TOT; i += gridDim.x * blockDim.x) {
        const float4* src;
        __half2* dst;
        int j = i;
        if (j < N4_X)                    { src = x;   dst = (__half2*)g_x; }
        else if ((j -= N4_X)   < N4_W1S) { src = sw1; dst = (__half2*)g_w1s; }
        else if ((j -= N4_W1S) < N4_W2S) { src = sw2; dst = (__half2*)g_w2s; }
        else if ((j -= N4_W2S) < N4_W1R) { src = rw1; dst = (__half2*)g_w1r; }
        else { j -= N4_W1R;              src = rw2; dst = (__half2*)g_w2r; }
        float4 v = src[j];
        dst[2*j]   = __halves2half2(__float2half_rn(v.x), __float2half_rn(v.y));
        dst[2*j+1] = __halves2half2(__float2half_rn(v.z), __float2half_rn(v.w));
    }
}

// ---- K1: router + slot assignment (one warp per token) ----
__global__ void k_router(const float* __restrict__ x,
                         const float* __restrict__ gw,
                         const float* __restrict__ gb) {
    int warp = (blockIdx.x * blockDim.x + threadIdx.x) >> 5;
    int lane = threadIdx.x & 31;
    if (warp >= T_TOK) return;
    const float* xr = x + warp * D_DIM;
    float xv[16];
#pragma unroll
    for (int i = 0; i < 16; i++) xv[i] = xr[lane + 32 * i];
    float acc[E_EXP];
#pragma unroll
    for (int e = 0; e < E_EXP; e++) acc[e] = 0.f;
#pragma unroll
    for (int i = 0; i < 16; i++) {
        int d = lane + 32 * i;
#pragma unroll
        for (int e = 0; e < E_EXP; e++) acc[e] += xv[i] * gw[e * D_DIM + d];
    }
#pragma unroll
    for (int e = 0; e < E_EXP; e++) {
#pragma unroll
        for (int off = 16; off; off >>= 1)
            acc[e] += __shfl_xor_sync(0xffffffffu, acc[e], off);
    }
    if (lane == 0) {
        float lg[E_EXP], mx = -1e30f;
#pragma unroll
        for (int e = 0; e < E_EXP; e++) { lg[e] = acc[e] + gb[e]; mx = fmaxf(mx, lg[e]); }
        float s = 0.f;
#pragma unroll
        for (int e = 0; e < E_EXP; e++) { lg[e] = expf(lg[e] - mx); s += lg[e]; }
        float inv = 1.f / s;
#pragma unroll
        for (int e = 0; e < E_EXP; e++) lg[e] *= inv;
        int i1 = 0; float v1 = -1.f;
#pragma unroll
        for (int e = 0; e < E_EXP; e++) { if (lg[e] > v1) { v1 = lg[e]; i1 = e; } }
        int i2 = -1; float v2 = -1.f;
#pragma unroll
        for (int e = 0; e < E_EXP; e++) { if (e != i1 && lg[e] > v2) { v2 = lg[e]; i2 = e; } }
        int r1 = i1 * T_TOK + atomicAdd(&g_cursor[i1], 1);
        int r2 = i2 * T_TOK + atomicAdd(&g_cursor[i2], 1);
        g_wt[warp * 2 + 0] = v1;  g_rows[warp * 2 + 0] = r1;  g_row_token[r1] = warp;
        g_wt[warp * 2 + 1] = v2;  g_rows[warp * 2 + 1] = r2;  g_row_token[r2] = warp;
    }
}

// ==================== merged mma.sync GEMM ====================
// LAYER 1: z<NS shared FFN1 plane z; z>=NS routed expert z-NS (token gather).
// LAYER 2: z<NS shared FFN2 plane z (z=0 -> out+biases, z=1 -> g_Os); z>=NS routed FFN2.
template<int LAYER>
__global__ void __launch_bounds__(256, 2) k_mma(
    const float* __restrict__ bias_s, const float* __restrict__ bias_r,
    float* __restrict__ outF) {
    int z = blockIdx.z;
    bool routed = (z >= NS_SH);
    int e = z - NS_SH;
    int row0;
    if (routed) {
        if ((int)blockIdx.y * BM >= g_cursor[e]) return;
        row0 = e * T_TOK + blockIdx.y * BM;
    } else {
        row0 = blockIdx.y * BM;
    }
    int col0 = blockIdx.x * BN;

    const int KA = (LAYER == 1) ? D_DIM : F_DIM;
    const int NK = KA / CK;

    const __half *A0, *B0;
    if (LAYER == 1) {
        A0 = g_x;
        B0 = routed ? (g_w1r + (size_t)e * F_DIM * D_DIM)
                    : (g_w1s + (size_t)z * F_DIM * D_DIM);
    } else {
        if (routed) {
            A0 = g_Hr;   // row0 already includes e*T_TOK
            B0 = g_w2r + (size_t)e * D_DIM * F_DIM;
        } else {
            A0 = g_Hs + (size_t)z * T_TOK * F_DIM;
            B0 = g_w2s + (size_t)z * D_DIM * F_DIM;
        }
    }

    extern __shared__ __align__(128) char dsm[];
    __shared__ int s_tok[BM];
    uint32_t sbase = smem_u32(dsm);

    int tid = threadIdx.x, wid = tid >> 5, lane = tid & 31;

    if (LAYER == 1) {
        // gather map (identity for shared planes)
        for (int i = tid; i < BM; i += 256)
            s_tok[i] = routed ? g_row_token[row0 + i] : (row0 + i);
        __syncthreads();
    }

    auto load_chunk = [&](int ci) {
        uint32_t sb = sbase + (ci % STAGES) * STAGE_B;
        int kk = ci * CK;
#pragma unroll
        for (int j = 0; j < 4; j++) {
            int idx = tid + j * 256;            // 0..1023
            int r = idx >> 3, u = idx & 7;
            uint32_t so = r * 128 + ((u ^ (r & 7)) * 16);
            int ar = (LAYER == 1) ? s_tok[r] : (row0 + r);
            cp16(sb + so,           A0 + (size_t)ar * KA + kk + u * 8);
            cp16(sb + PLANE_B + so, B0 + (size_t)(col0 + r) * KA + kk + u * 8);
        }
        cp_commit();
    };

    // warp layout: 2x4 grid of 64x32 warp tiles
    int wr = (wid >> 2) * 64, wc = (wid & 3) * 32;
    int grp = lane >> 2, qp = lane & 3;
    int rl = lane & 15, hi = lane >> 4;

    float c[4][4][4];
#pragma unroll
    for (int i = 0; i < 4; i++)
#pragma unroll
        for (int j = 0; j < 4; j++)
#pragma unroll
            for (int q = 0; q < 4; q++) c[i][j][q] = 0.f;

    int npre = NK < STAGES ? NK : STAGES;
    for (int ci = 0; ci < npre; ci++) load_chunk(ci);

    uint32_t ah[2][4][4], bq[2][4][2];     // double-buffered fragments

    auto ld_frags = [&](uint32_t sb, int ks, int pb) {
        int cch = 2 * ks + hi;
#pragma unroll
        for (int mt = 0; mt < 4; mt++) {
            int r = wr + mt * 16 + rl;
            uint32_t ad = sb + r * 128 + ((cch ^ (r & 7)) << 4);
            ldsm4(ah[pb][mt][0], ah[pb][mt][1], ah[pb][mt][2], ah[pb][mt][3], ad);
        }
#pragma unroll
        for (int p = 0; p < 2; p++) {
            int r = wc + p * 16 + rl;
            uint32_t ad = sb + PLANE_B + r * 128 + ((cch ^ (r & 7)) << 4);
            uint32_t q0, q1, q2, q3;
            ldsm4(q0, q1, q2, q3, ad);
            bq[pb][2*p][0] = q0; bq[pb][2*p+1][0] = q1;
            bq[pb][2*p][1] = q2; bq[pb][2*p+1][1] = q3;
        }
    };

    for (int i = 0; i < NK; i++) {
        int issued = (NK < i + STAGES) ? NK : (i + STAGES);
        int pend = issued - i - 1;
        if (pend >= 2)      asm volatile("cp.async.wait_group 2;" ::: "memory");
        else if (pend == 1) asm volatile("cp.async.wait_group 1;" ::: "memory");
        else                asm volatile("cp.async.wait_group 0;" ::: "memory");
        __syncthreads();
        uint32_t sb = sbase + (i % STAGES) * STAGE_B;

        ld_frags(sb, 0, 0);
#pragma unroll
        for (int ks = 0; ks < 4; ks++) {
            int cur = ks & 1;
            if (ks < 3) ld_frags(sb, ks + 1, cur ^ 1);
#pragma unroll
            for (int mt = 0; mt < 4; mt++)
#pragma unroll
                for (int nt = 0; nt < 4; nt++)
                    mma_f16(c[mt][nt][0], c[mt][nt][1], c[mt][nt][2], c[mt][nt][3],
                            ah[cur][mt][0], ah[cur][mt][1], ah[cur][mt][2], ah[cur][mt][3],
                            bq[cur][nt][0], bq[cur][nt][1]);
        }
        __syncthreads();
        if (i + STAGES < NK) load_chunk(i + STAGES);
    }

    // ---- epilogue ----
#pragma unroll
    for (int mt = 0; mt < 4; ++mt) {
        int r = row0 + wr + mt * 16 + grp;
#pragma unroll
        for (int nt = 0; nt < 4; ++nt) {
            int cg = col0 + wc + nt * 8 + qp * 2;
            float c0 = c[mt][nt][0], c1 = c[mt][nt][1];
            float c2 = c[mt][nt][2], c3 = c[mt][nt][3];
            if (LAYER == 1) {
                const float* bz = routed ? (bias_r + (size_t)e * F_DIM)
                                         : (bias_s + (size_t)z * F_DIM);
                float b0 = bz[cg], b1 = bz[cg + 1];
                float h0 = gelu_exact(c0 + b0), h1 = gelu_exact(c1 + b1);
                float h2 = gelu_exact(c2 + b0), h3 = gelu_exact(c3 + b1);
                __half* Hh = routed ? g_Hr : (g_Hs + (size_t)z * T_TOK * F_DIM);
                size_t rr = routed ? (size_t)(r - 0) : (size_t)r;  // row0 already absolute for Hr
                *(__half2*)(Hh + rr * F_DIM + cg) =
                    __halves2half2(__float2half_rn(h0), __float2half_rn(h1));
                *(__half2*)(Hh + (rr + 8) * F_DIM + cg) =
                    __halves2half2(__float2half_rn(h2), __float2half_rn(h3));
            } else {
                if (routed) {
                    const float* bz = bias_r + (size_t)e * D_DIM;
                    float b0 = bz[cg], b1 = bz[cg + 1];
                    float2 v;
                    v.x = c0 + b0; v.y = c1 + b1;
                    *(float2*)&g_Or[(size_t)r * D_DIM + cg] = v;
                    v.x = c2 + b0; v.y = c3 + b1;
                    *(float2*)&g_Or[(size_t)(r + 8) * D_DIM + cg] = v;
                } else if (z == 0) {
                    float b0 = bias_s[cg] + bias_s[D_DIM + cg];
                    float b1 = bias_s[cg + 1] + bias_s[D_DIM + cg + 1];
                    float2 v;
                    v.x = c0 + b0; v.y = c1 + b1;
                    *(float2*)&outF[(size_t)r * D_DIM + cg] = v;
                    v.x = c2 + b0; v.y = c3 + b1;
                    *(float2*)&outF[(size_t)(r + 8) * D_DIM + cg] = v;
                } else {
                    float2 v;
                    v.x = c0; v.y = c1;
                    *(float2*)&g_Os[(size_t)r * D_DIM + cg] = v;
                    v.x = c2; v.y = c3;
                    *(float2*)&g_Os[(size_t)(r + 8) * D_DIM + cg] = v;
                }
            }
        }
    }
}

// ---- combine: out += shared plane-1 partial + weighted routed ----
__global__ void k_combine(float* __restrict__ out) {
    int idx = blockIdx.x * blockDim.x + threadIdx.x;
    if (idx >= T_TOK * (D_DIM / 4)) return;
    int t = idx >> 7;
    int dq = idx & 127;
    float4 o = ((float4*)out)[t * 128 + dq];
    float4 s = ((const float4*)g_Os)[t * 128 + dq];
    int r0 = g_rows[t * 2 + 0], r1 = g_rows[t * 2 + 1];
    float w0 = g_wt[t * 2 + 0], w1 = g_wt[t * 2 + 1];
    float4 a = ((const float4*)g_Or)[(size_t)r0 * 128 + dq];
    float4 b = ((const float4*)g_Or)[(size_t)r1 * 128 + dq];
    o.x += s.x + w0 * a.x + w1 * b.x;
    o.y += s.y + w0 * a.y + w1 * b.y;
    o.z += s.z + w0 * a.z + w1 * b.z;
    o.w += s.w + w0 * a.w + w1 * b.w;
    ((float4*)out)[t * 128 + dq] = o;
}

extern "C" void kernel_launch(void* const* d_in, const int* in_sizes, int n_in,
                              void* d_out, int out_size) {
    const float* x   = (const float*)d_in[0];
    const float* gw  = (const float*)d_in[1];
    const float* gb  = (const float*)d_in[2];
    const float* sw1 = (const float*)d_in[3];
    const float* sb1 = (const float*)d_in[4];
    const float* sw2 = (const float*)d_in[5];
    const float* sb2 = (const float*)d_in[6];
    const float* rw1 = (const float*)d_in[7];
    const float* rb1 = (const float*)d_in[8];
    const float* rw2 = (const float*)d_in[9];
    const float* rb2 = (const float*)d_in[10];
    float* out = (float*)d_out;

    static int smem_set = 0;
    if (!smem_set) {
        cudaFuncSetAttribute(k_mma<1>, cudaFuncAttributeMaxDynamicSharedMemorySize, DSMEM_B);
        cudaFuncSetAttribute(k_mma<2>, cudaFuncAttributeMaxDynamicSharedMemorySize, DSMEM_B);
        smem_set = 1;
    }

    // fused conversion (all weights + x) + state reset
    k_cvt_all<<<5632, 256>>>((const float4*)x, (const float4*)sw1, (const float4*)sw2,
                             (const float4*)rw1, (const float4*)rw2);
    // router + slot assignment
    k_router<<<T_TOK / 8, 256>>>(x, gw, gb);

    dim3 blk(256);
    // FFN1: shared planes + routed experts in one launch
    k_mma<1><<<dim3(F_DIM / BN, T_TOK / BM, NS_SH + E_EXP), blk, DSMEM_B>>>(sb1, rb1, nullptr);
    // FFN2: shared planes + routed experts in one launch
    k_mma<2><<<dim3(D_DIM / BN, T_TOK / BM, NS_SH + E_EXP), blk, DSMEM_B>>>(sb2, rb2, out);
    // combine
    k_combine<<<(T_TOK * (D_DIM / 4) + 255) / 256, 256>>>(out);
}

// round 16
// speedup vs baseline: 12.5062x; 1.0063x over previous
#include <cuda_runtime.h>
#include <cuda_fp16.h>
#include <math.h>
#include <stdint.h>

// Problem constants
#define T_TOK 4096
#define D_DIM 512
#define F_DIM 2048
#define E_EXP 8
#define NS_SH 2
#define TOPK 2

// GEMM tiling
#define BM 128
#define BN 128
#define CK 64                         // K elems per chunk (128B fp16 rows)
#define STAGES 3
#define PLANE_B 16384                 // 128 rows * 128 B
#define STAGE_B (2*PLANE_B)           // A, B
#define DSMEM_B (STAGES*STAGE_B)      // 98304

#define ROWS_CAP (E_EXP*T_TOK)        // fixed per-expert segments (32768 rows)

// conversion region sizes (in float4 units)
#define N4_X   ((T_TOK*D_DIM)/4)
#define N4_W1S ((NS_SH*F_DIM*D_DIM)/4)
#define N4_W2S ((NS_SH*D_DIM*F_DIM)/4)
#define N4_W1R ((E_EXP*F_DIM*D_DIM)/4)
#define N4_W2R ((E_EXP*D_DIM*F_DIM)/4)
#define N4_TOT (N4_X+N4_W1S+N4_W2S+N4_W1R+N4_W2R)

// ---- device scratch (allocation-free rule: __device__ globals) ----
__device__ __align__(128) __half g_x  [T_TOK*D_DIM];
__device__ __align__(128) __half g_w1s[NS_SH*F_DIM*D_DIM];
__device__ __align__(128) __half g_w2s[NS_SH*D_DIM*F_DIM];
__device__ __align__(128) __half g_w1r[E_EXP*F_DIM*D_DIM];
__device__ __align__(128) __half g_w2r[E_EXP*D_DIM*F_DIM];
__device__ __align__(128) __half g_Hs [NS_SH*T_TOK*F_DIM];
__device__ __align__(128) __half g_Hr [(size_t)ROWS_CAP*F_DIM];   // 128 MB
__device__ __align__(128) float g_Or[(size_t)ROWS_CAP*D_DIM];     // 64 MB
__device__ __align__(128) float g_Os[T_TOK*D_DIM];                // shared FFN2 plane-1 partial
// routing state
__device__ int   g_cursor[E_EXP];
__device__ float g_wt[T_TOK * TOPK];
__device__ int   g_rows[T_TOK * TOPK];
__device__ int   g_row_token[ROWS_CAP];

__device__ __forceinline__ float gelu_exact(float v) {
    return 0.5f * v * (1.0f + erff(v * 0.70710678118654752440f));
}

// ================= PTX helpers =================
__device__ __forceinline__ uint32_t smem_u32(const void* p) {
    uint32_t a;
    asm("{ .reg .u64 t; cvta.to.shared.u64 t, %1; cvt.u32.u64 %0, t; }" : "=r"(a) : "l"(p));
    return a;
}
__device__ __forceinline__ void cp16(uint32_t s, const void* g) {
    asm volatile("cp.async.cg.shared.global [%0], [%1], 16;\n" :: "r"(s), "l"(g));
}
__device__ __forceinline__ void cp_commit() {
    asm volatile("cp.async.commit_group;\n" ::: "memory");
}
__device__ __forceinline__ void ldsm4(uint32_t& r0, uint32_t& r1, uint32_t& r2, uint32_t& r3,
                                      uint32_t addr) {
    asm volatile("ldmatrix.sync.aligned.m8n8.x4.shared.b16 {%0,%1,%2,%3}, [%4];"
                 : "=r"(r0), "=r"(r1), "=r"(r2), "=r"(r3) : "r"(addr));
}
__device__ __forceinline__ void mma_f16(float& c0, float& c1, float& c2, float& c3,
                                        uint32_t a0, uint32_t a1, uint32_t a2, uint32_t a3,
                                        uint32_t b0, uint32_t b1) {
    asm volatile(
        "mma.sync.aligned.m16n8k16.row.col.f32.f16.f16.f32 "
        "{%0,%1,%2,%3},{%4,%5,%6,%7},{%8,%9},{%0,%1,%2,%3};\n"
        : "+f"(c0), "+f"(c1), "+f"(c2), "+f"(c3)
        : "r"(a0), "r"(a1), "r"(a2), "r"(a3), "r"(b0), "r"(b1));
}

// ---- fused: fp32 -> fp16 for all 5 tensors + per-call state reset ----
__global__ void k_cvt_all(const float4* __restrict__ x,   const float4* __restrict__ sw1,
                          const float4* __restrict__ sw2, const float4* __restrict__ rw1,
                          const float4* __restrict__ rw2) {
    int gi = blockIdx.x * blockDim.x + threadIdx.x;
    if (gi < E_EXP) g_cursor[gi] = 0;
    if (gi < ROWS_CAP) g_row_token[gi] = 0;

    for (int i = gi; i < N4_TOT; i += gridDim.x * blockDim.x) {
        const float4* src;
        __half2* dst;
        int j = i;
        if (j < N4_X)                    { src = x;   dst = (__half2*)g_x; }
        else if ((j -= N4_X)   < N4_W1S) { src = sw1; dst = (__half2*)g_w1s; }
        else if ((j -= N4_W1S) < N4_W2S) { src = sw2; dst = (__half2*)g_w2s; }
        else if ((j -= N4_W2S) < N4_W1R) { src = rw1; dst = (__half2*)g_w1r; }
        else { j -= N4_W1R;              src = rw2; dst = (__half2*)g_w2r; }
        float4 v = src[j];
        dst[2*j]   = __halves2half2(__float2half_rn(v.x), __float2half_rn(v.y));
        dst[2*j+1] = __halves2half2(__float2half_rn(v.z), __float2half_rn(v.w));
    }
}

// ---- K1: router + slot assignment (one warp per token) ----
__global__ void k_router(const float* __restrict__ x,
                         const float* __restrict__ gw,
                         const float* __restrict__ gb) {
    int warp = (blockIdx.x * blockDim.x + threadIdx.x) >> 5;
    int lane = threadIdx.x & 31;
    if (warp >= T_TOK) return;
    const float* xr = x + warp * D_DIM;
    float xv[16];
#pragma unroll
    for (int i = 0; i < 16; i++) xv[i] = xr[lane + 32 * i];
    float acc[E_EXP];
#pragma unroll
    for (int e = 0; e < E_EXP; e++) acc[e] = 0.f;
#pragma unroll
    for (int i = 0; i < 16; i++) {
        int d = lane + 32 * i;
#pragma unroll
        for (int e = 0; e < E_EXP; e++) acc[e] += xv[i] * gw[e * D_DIM + d];
    }
#pragma unroll
    for (int e = 0; e < E_EXP; e++) {
#pragma unroll
        for (int off = 16; off; off >>= 1)
            acc[e] += __shfl_xor_sync(0xffffffffu, acc[e], off);
    }
    if (lane == 0) {
        float lg[E_EXP], mx = -1e30f;
#pragma unroll
        for (int e = 0; e < E_EXP; e++) { lg[e] = acc[e] + gb[e]; mx = fmaxf(mx, lg[e]); }
        float s = 0.f;
#pragma unroll
        for (int e = 0; e < E_EXP; e++) { lg[e] = expf(lg[e] - mx); s += lg[e]; }
        float inv = 1.f / s;
#pragma unroll
        for (int e = 0; e < E_EXP; e++) lg[e] *= inv;
        int i1 = 0; float v1 = -1.f;
#pragma unroll
        for (int e = 0; e < E_EXP; e++) { if (lg[e] > v1) { v1 = lg[e]; i1 = e; } }
        int i2 = -1; float v2 = -1.f;
#pragma unroll
        for (int e = 0; e < E_EXP; e++) { if (e != i1 && lg[e] > v2) { v2 = lg[e]; i2 = e; } }
        int r1 = i1 * T_TOK + atomicAdd(&g_cursor[i1], 1);
        int r2 = i2 * T_TOK + atomicAdd(&g_cursor[i2], 1);
        g_wt[warp * 2 + 0] = v1;  g_rows[warp * 2 + 0] = r1;  g_row_token[r1] = warp;
        g_wt[warp * 2 + 1] = v2;  g_rows[warp * 2 + 1] = r2;  g_row_token[r2] = warp;
    }
}

// ==================== merged mma.sync GEMM (single-barrier multistage) ====================
// LAYER 1: z<NS shared FFN1 plane z; z>=NS routed expert z-NS (token gather).
// LAYER 2: z<NS shared FFN2 plane z (z=0 -> out+biases, z=1 -> g_Os); z>=NS routed FFN2.
template<int LAYER>
__global__ void __launch_bounds__(256, 2) k_mma(
    const float* __restrict__ bias_s, const float* __restrict__ bias_r,
    float* __restrict__ outF) {
    int z = blockIdx.z;
    bool routed = (z >= NS_SH);
    int e = z - NS_SH;
    int row0;
    if (routed) {
        if ((int)blockIdx.y * BM >= g_cursor[e]) return;
        row0 = e * T_TOK + blockIdx.y * BM;
    } else {
        row0 = blockIdx.y * BM;
    }
    int col0 = blockIdx.x * BN;

    const int KA = (LAYER == 1) ? D_DIM : F_DIM;
    const int NK = KA / CK;

    const __half *A0, *B0;
    if (LAYER == 1) {
        A0 = g_x;
        B0 = routed ? (g_w1r + (size_t)e * F_DIM * D_DIM)
                    : (g_w1s + (size_t)z * F_DIM * D_DIM);
    } else {
        if (routed) {
            A0 = g_Hr;   // row0 already includes e*T_TOK
            B0 = g_w2r + (size_t)e * D_DIM * F_DIM;
        } else {
            A0 = g_Hs + (size_t)z * T_TOK * F_DIM;
            B0 = g_w2s + (size_t)z * D_DIM * F_DIM;
        }
    }

    extern __shared__ __align__(128) char dsm[];
    __shared__ int s_tok[BM];
    uint32_t sbase = smem_u32(dsm);

    int tid = threadIdx.x, wid = tid >> 5, lane = tid & 31;

    if (LAYER == 1) {
        // gather map (identity for shared planes)
        for (int i = tid; i < BM; i += 256)
            s_tok[i] = routed ? g_row_token[row0 + i] : (row0 + i);
        __syncthreads();
    }

    auto load_chunk = [&](int ci) {
        uint32_t sb = sbase + (ci % STAGES) * STAGE_B;
        int kk = ci * CK;
#pragma unroll
        for (int j = 0; j < 4; j++) {
            int idx = tid + j * 256;            // 0..1023
            int r = idx >> 3, u = idx & 7;
            uint32_t so = r * 128 + ((u ^ (r & 7)) * 16);
            int ar = (LAYER == 1) ? s_tok[r] : (row0 + r);
            cp16(sb + so,           A0 + (size_t)ar * KA + kk + u * 8);
            cp16(sb + PLANE_B + so, B0 + (size_t)(col0 + r) * KA + kk + u * 8);
        }
        cp_commit();
    };

    // warp layout: 2x4 grid of 64x32 warp tiles
    int wr = (wid >> 2) * 64, wc = (wid & 3) * 32;
    int grp = lane >> 2, qp = lane & 3;
    int rl = lane & 15, hi = lane >> 4;

    float c[4][4][4];
#pragma unroll
    for (int i = 0; i < 4; i++)
#pragma unroll
        for (int j = 0; j < 4; j++)
#pragma unroll
            for (int q = 0; q < 4; q++) c[i][j][q] = 0.f;

    // prefetch STAGES-1 chunks
    int npre = NK < (STAGES - 1) ? NK : (STAGES - 1);
    for (int ci = 0; ci < npre; ci++) load_chunk(ci);

    uint32_t ah[2][4][4], bq[2][4][2];     // double-buffered fragments

    auto ld_frags = [&](uint32_t sb, int ks, int pb) {
        int cch = 2 * ks + hi;
#pragma unroll
        for (int mt = 0; mt < 4; mt++) {
            int r = wr + mt * 16 + rl;
            uint32_t ad = sb + r * 128 + ((cch ^ (r & 7)) << 4);
            ldsm4(ah[pb][mt][0], ah[pb][mt][1], ah[pb][mt][2], ah[pb][mt][3], ad);
        }
#pragma unroll
        for (int p = 0; p < 2; p++) {
            int r = wc + p * 16 + rl;
            uint32_t ad = sb + PLANE_B + r * 128 + ((cch ^ (r & 7)) << 4);
            uint32_t q0, q1, q2, q3;
            ldsm4(q0, q1, q2, q3, ad);
            bq[pb][2*p][0] = q0; bq[pb][2*p+1][0] = q1;
            bq[pb][2*p][1] = q2; bq[pb][2*p+1][1] = q3;
        }
    };

    for (int i = 0; i < NK; i++) {
        // wait for chunk i: allow (issued - i - 1) groups outstanding
        int issued = (NK < i + STAGES - 1) ? NK : (i + STAGES - 1);
        int pend = issued - i - 1;
        if (pend >= 1) asm volatile("cp.async.wait_group 1;" ::: "memory");
        else           asm volatile("cp.async.wait_group 0;" ::: "memory");
        __syncthreads();   // single barrier: chunk i visible to all; slot (i-1)%S free

        // prefetch chunk i+STAGES-1 into the slot freed by iter i-1
        if (i + STAGES - 1 < NK) load_chunk(i + STAGES - 1);

        uint32_t sb = sbase + (i % STAGES) * STAGE_B;
        ld_frags(sb, 0, 0);
#pragma unroll
        for (int ks = 0; ks < 4; ks++) {
            int cur = ks & 1;
            if (ks < 3) ld_frags(sb, ks + 1, cur ^ 1);
#pragma unroll
            for (int mt = 0; mt < 4; mt++)
#pragma unroll
                for (int nt = 0; nt < 4; nt++)
                    mma_f16(c[mt][nt][0], c[mt][nt][1], c[mt][nt][2], c[mt][nt][3],
                            ah[cur][mt][0], ah[cur][mt][1], ah[cur][mt][2], ah[cur][mt][3],
                            bq[cur][nt][0], bq[cur][nt][1]);
        }
    }

    // ---- epilogue ----
#pragma unroll
    for (int mt = 0; mt < 4; ++mt) {
        int r = row0 + wr + mt * 16 + grp;
#pragma unroll
        for (int nt = 0; nt < 4; ++nt) {
            int cg = col0 + wc + nt * 8 + qp * 2;
            float c0 = c[mt][nt][0], c1 = c[mt][nt][1];
            float c2 = c[mt][nt][2], c3 = c[mt][nt][3];
            if (LAYER == 1) {
                const float* bz = routed ? (bias_r + (size_t)e * F_DIM)
                                         : (bias_s + (size_t)z * F_DIM);
                float b0 = bz[cg], b1 = bz[cg + 1];
                float h0 = gelu_exact(c0 + b0), h1 = gelu_exact(c1 + b1);
                float h2 = gelu_exact(c2 + b0), h3 = gelu_exact(c3 + b1);
                __half* Hh = routed ? g_Hr : (g_Hs + (size_t)z * T_TOK * F_DIM);
                *(__half2*)(Hh + (size_t)r * F_DIM + cg) =
                    __halves2half2(__float2half_rn(h0), __float2half_rn(h1));
                *(__half2*)(Hh + (size_t)(r + 8) * F_DIM + cg) =
                    __halves2half2(__float2half_rn(h2), __float2half_rn(h3));
            } else {
                if (routed) {
                    const float* bz = bias_r + (size_t)e * D_DIM;
                    float b0 = bz[cg], b1 = bz[cg + 1];
                    float2 v;
                    v.x = c0 + b0; v.y = c1 + b1;
                    *(float2*)&g_Or[(size_t)r * D_DIM + cg] = v;
                    v.x = c2 + b0; v.y = c3 + b1;
                    *(float2*)&g_Or[(size_t)(r + 8) * D_DIM + cg] = v;
                } else if (z == 0) {
                    float b0 = bias_s[cg] + bias_s[D_DIM + cg];
                    float b1 = bias_s[cg + 1] + bias_s[D_DIM + cg + 1];
                    float2 v;
                    v.x = c0 + b0; v.y = c1 + b1;
                    *(float2*)&outF[(size_t)r * D_DIM + cg] = v;
                    v.x = c2 + b0; v.y = c3 + b1;
                    *(float2*)&outF[(size_t)(r + 8) * D_DIM + cg] = v;
                } else {
                    float2 v;
                    v.x = c0; v.y = c1;
                    *(float2*)&g_Os[(size_t)r * D_DIM + cg] = v;
                    v.x = c2; v.y = c3;
                    *(float2*)&g_Os[(size_t)(r + 8) * D_DIM + cg] = v;
                }
            }
        }
    }
}

// ---- combine: out += shared plane-1 partial + weighted routed ----
__global__ void k_combine(float* __restrict__ out) {
    int idx = blockIdx.x * blockDim.x + threadIdx.x;
    if (idx >= T_TOK * (D_DIM / 4)) return;
    int t = idx >> 7;
    int dq = idx & 127;
    float4 o = ((float4*)out)[t * 128 + dq];
    float4 s = ((const float4*)g_Os)[t * 128 + dq];
    int r0 = g_rows[t * 2 + 0], r1 = g_rows[t * 2 + 1];
    float w0 = g_wt[t * 2 + 0], w1 = g_wt[t * 2 + 1];
    float4 a = ((const float4*)g_Or)[(size_t)r0 * 128 + dq];
    float4 b = ((const float4*)g_Or)[(size_t)r1 * 128 + dq];
    o.x += s.x + w0 * a.x + w1 * b.x;
    o.y += s.y + w0 * a.y + w1 * b.y;
    o.z += s.z + w0 * a.z + w1 * b.z;
    o.w += s.w + w0 * a.w + w1 * b.w;
    ((float4*)out)[t * 128 + dq] = o;
}

extern "C" void kernel_launch(void* const* d_in, const int* in_sizes, int n_in,
                              void* d_out, int out_size) {
    const float* x   = (const float*)d_in[0];
    const float* gw  = (const float*)d_in[1];
    const float* gb  = (const float*)d_in[2];
    const float* sw1 = (const float*)d_in[3];
    const float* sb1 = (const float*)d_in[4];
    const float* sw2 = (const float*)d_in[5];
    const float* sb2 = (const float*)d_in[6];
    const float* rw1 = (const float*)d_in[7];
    const float* rb1 = (const float*)d_in[8];
    const float* rw2 = (const float*)d_in[9];
    const float* rb2 = (const float*)d_in[10];
    float* out = (float*)d_out;

    static int smem_set = 0;
    if (!smem_set) {
        cudaFuncSetAttribute(k_mma<1>, cudaFuncAttributeMaxDynamicSharedMemorySize, DSMEM_B);
        cudaFuncSetAttribute(k_mma<2>, cudaFuncAttributeMaxDynamicSharedMemorySize, DSMEM_B);
        smem_set = 1;
    }

    // fused conversion (all weights + x) + state reset
    k_cvt_all<<<5632, 256>>>((const float4*)x, (const float4*)sw1, (const float4*)sw2,
                             (const float4*)rw1, (const float4*)rw2);
    // router + slot assignment
    k_router<<<T_TOK / 8, 256>>>(x, gw, gb);

    dim3 blk(256);
    // FFN1: shared planes + routed experts in one launch
    k_mma<1><<<dim3(F_DIM / BN, T_TOK / BM, NS_SH + E_EXP), blk, DSMEM_B>>>(sb1, rb1, nullptr);
    // FFN2: shared planes + routed experts in one launch
    k_mma<2><<<dim3(D_DIM / BN, T_TOK / BM, NS_SH + E_EXP), blk, DSMEM_B>>>(sb2, rb2, out);
    // combine
    k_combine<<<(T_TOK * (D_DIM / 4) + 255) / 256, 256>>>(out);
}

// round 17
// speedup vs baseline: 12.5802x; 1.0059x over previous
#include <cuda_runtime.h>
#include <cuda_fp16.h>
#include <math.h>
#include <stdint.h>

// Problem constants
#define T_TOK 4096
#define D_DIM 512
#define F_DIM 2048
#define E_EXP 8
#define NS_SH 2
#define TOPK 2

// GEMM tiling
#define BM 128
#define BN 128
#define CK 64                         // K elems per chunk (128B fp16 rows)
#define STAGES 3
#define PLANE_B 16384                 // 128 rows * 128 B
#define STAGE_B (2*PLANE_B)           // A, B
#define DSMEM_B (STAGES*STAGE_B)      // 98304
#define TMMA 128                      // threads per GEMM CTA (4 warps, 64x64 warp tiles)

#define ROWS_CAP (E_EXP*T_TOK)        // fixed per-expert segments (32768 rows)

// conversion region sizes (in float4 units)
#define N4_X   ((T_TOK*D_DIM)/4)
#define N4_W1S ((NS_SH*F_DIM*D_DIM)/4)
#define N4_W2S ((NS_SH*D_DIM*F_DIM)/4)
#define N4_W1R ((E_EXP*F_DIM*D_DIM)/4)
#define N4_W2R ((E_EXP*D_DIM*F_DIM)/4)
#define N4_TOT (N4_X+N4_W1S+N4_W2S+N4_W1R+N4_W2R)

// ---- device scratch (allocation-free rule: __device__ globals) ----
__device__ __align__(128) __half g_x  [T_TOK*D_DIM];
__device__ __align__(128) __half g_w1s[NS_SH*F_DIM*D_DIM];
__device__ __align__(128) __half g_w2s[NS_SH*D_DIM*F_DIM];
__device__ __align__(128) __half g_w1r[E_EXP*F_DIM*D_DIM];
__device__ __align__(128) __half g_w2r[E_EXP*D_DIM*F_DIM];
__device__ __align__(128) __half g_Hs [NS_SH*T_TOK*F_DIM];
__device__ __align__(128) __half g_Hr [(size_t)ROWS_CAP*F_DIM];   // 128 MB
__device__ __align__(128) float g_Or[(size_t)ROWS_CAP*D_DIM];     // 64 MB
__device__ __align__(128) float g_Os[T_TOK*D_DIM];                // shared FFN2 plane-1 partial
// routing state
__device__ int   g_cursor[E_EXP];
__device__ float g_wt[T_TOK * TOPK];
__device__ int   g_rows[T_TOK * TOPK];
__device__ int   g_row_token[ROWS_CAP];

__device__ __forceinline__ float gelu_exact(float v) {
    return 0.5f * v * (1.0f + erff(v * 0.70710678118654752440f));
}

// ================= PTX helpers =================
__device__ __forceinline__ uint32_t smem_u32(const void* p) {
    uint32_t a;
    asm("{ .reg .u64 t; cvta.to.shared.u64 t, %1; cvt.u32.u64 %0, t; }" : "=r"(a) : "l"(p));
    return a;
}
__device__ __forceinline__ void cp16(uint32_t s, const void* g) {
    asm volatile("cp.async.cg.shared.global [%0], [%1], 16;\n" :: "r"(s), "l"(g));
}
__device__ __forceinline__ void cp_commit() {
    asm volatile("cp.async.commit_group;\n" ::: "memory");
}
__device__ __forceinline__ void ldsm4(uint32_t& r0, uint32_t& r1, uint32_t& r2, uint32_t& r3,
                                      uint32_t addr) {
    asm volatile("ldmatrix.sync.aligned.m8n8.x4.shared.b16 {%0,%1,%2,%3}, [%4];"
                 : "=r"(r0), "=r"(r1), "=r"(r2), "=r"(r3) : "r"(addr));
}
__device__ __forceinline__ void mma_f16(float& c0, float& c1, float& c2, float& c3,
                                        uint32_t a0, uint32_t a1, uint32_t a2, uint32_t a3,
                                        uint32_t b0, uint32_t b1) {
    asm volatile(
        "mma.sync.aligned.m16n8k16.row.col.f32.f16.f16.f32 "
        "{%0,%1,%2,%3},{%4,%5,%6,%7},{%8,%9},{%0,%1,%2,%3};\n"
        : "+f"(c0), "+f"(c1), "+f"(c2), "+f"(c3)
        : "r"(a0), "r"(a1), "r"(a2), "r"(a3), "r"(b0), "r"(b1));
}

// ---- fused: fp32 -> fp16 for all 5 tensors + per-call state reset ----
__global__ void k_cvt_all(const float4* __restrict__ x,   const float4* __restrict__ sw1,
                          const float4* __restrict__ sw2, const float4* __restrict__ rw1,
                          const float4* __restrict__ rw2) {
    int gi = blockIdx.x * blockDim.x + threadIdx.x;
    if (gi < E_EXP) g_cursor[gi] = 0;
    if (gi < ROWS_CAP) g_row_token[gi] = 0;

    for (int i = gi; i < N4_TOT; i += gridDim.x * blockDim.x) {
        const float4* src;
        __half2* dst;
        int j = i;
        if (j < N4_X)                    { src = x;   dst = (__half2*)g_x; }
        else if ((j -= N4_X)   < N4_W1S) { src = sw1; dst = (__half2*)g_w1s; }
        else if ((j -= N4_W1S) < N4_W2S) { src = sw2; dst = (__half2*)g_w2s; }
        else if ((j -= N4_W2S) < N4_W1R) { src = rw1; dst = (__half2*)g_w1r; }
        else { j -= N4_W1R;              src = rw2; dst = (__half2*)g_w2r; }
        float4 v = src[j];
        dst[2*j]   = __halves2half2(__float2half_rn(v.x), __float2half_rn(v.y));
        dst[2*j+1] = __halves2half2(__float2half_rn(v.z), __float2half_rn(v.w));
    }
}

// ---- K1: router + slot assignment (one warp per token) ----
__global__ void k_router(const float* __restrict__ x,
                         const float* __restrict__ gw,
                         const float* __restrict__ gb) {
    int warp = (blockIdx.x * blockDim.x + threadIdx.x) >> 5;
    int lane = threadIdx.x & 31;
    if (warp >= T_TOK) return;
    const float* xr = x + warp * D_DIM;
    float xv[16];
#pragma unroll
    for (int i = 0; i < 16; i++) xv[i] = xr[lane + 32 * i];
    float acc[E_EXP];
#pragma unroll
    for (int e = 0; e < E_EXP; e++) acc[e] = 0.f;
#pragma unroll
    for (int i = 0; i < 16; i++) {
        int d = lane + 32 * i;
#pragma unroll
        for (int e = 0; e < E_EXP; e++) acc[e] += xv[i] * gw[e * D_DIM + d];
    }
#pragma unroll
    for (int e = 0; e < E_EXP; e++) {
#pragma unroll
        for (int off = 16; off; off >>= 1)
            acc[e] += __shfl_xor_sync(0xffffffffu, acc[e], off);
    }
    if (lane == 0) {
        float lg[E_EXP], mx = -1e30f;
#pragma unroll
        for (int e = 0; e < E_EXP; e++) { lg[e] = acc[e] + gb[e]; mx = fmaxf(mx, lg[e]); }
        float s = 0.f;
#pragma unroll
        for (int e = 0; e < E_EXP; e++) { lg[e] = expf(lg[e] - mx); s += lg[e]; }
        float inv = 1.f / s;
#pragma unroll
        for (int e = 0; e < E_EXP; e++) lg[e] *= inv;
        int i1 = 0; float v1 = -1.f;
#pragma unroll
        for (int e = 0; e < E_EXP; e++) { if (lg[e] > v1) { v1 = lg[e]; i1 = e; } }
        int i2 = -1; float v2 = -1.f;
#pragma unroll
        for (int e = 0; e < E_EXP; e++) { if (e != i1 && lg[e] > v2) { v2 = lg[e]; i2 = e; } }
        int r1 = i1 * T_TOK + atomicAdd(&g_cursor[i1], 1);
        int r2 = i2 * T_TOK + atomicAdd(&g_cursor[i2], 1);
        g_wt[warp * 2 + 0] = v1;  g_rows[warp * 2 + 0] = r1;  g_row_token[r1] = warp;
        g_wt[warp * 2 + 1] = v2;  g_rows[warp * 2 + 1] = r2;  g_row_token[r2] = warp;
    }
}

// ==================== merged mma.sync GEMM (4 warps, 64x64 warp tiles) ====================
// LAYER 1: z<NS shared FFN1 plane z; z>=NS routed expert z-NS (token gather).
// LAYER 2: z<NS shared FFN2 plane z (z=0 -> out+biases, z=1 -> g_Os); z>=NS routed FFN2.
template<int LAYER>
__global__ void __launch_bounds__(TMMA, 2) k_mma(
    const float* __restrict__ bias_s, const float* __restrict__ bias_r,
    float* __restrict__ outF) {
    int z = blockIdx.z;
    bool routed = (z >= NS_SH);
    int e = z - NS_SH;
    int row0;
    if (routed) {
        if ((int)blockIdx.y * BM >= g_cursor[e]) return;
        row0 = e * T_TOK + blockIdx.y * BM;
    } else {
        row0 = blockIdx.y * BM;
    }
    int col0 = blockIdx.x * BN;

    const int KA = (LAYER == 1) ? D_DIM : F_DIM;
    const int NK = KA / CK;

    const __half *A0, *B0;
    if (LAYER == 1) {
        A0 = g_x;
        B0 = routed ? (g_w1r + (size_t)e * F_DIM * D_DIM)
                    : (g_w1s + (size_t)z * F_DIM * D_DIM);
    } else {
        if (routed) {
            A0 = g_Hr;   // row0 already includes e*T_TOK
            B0 = g_w2r + (size_t)e * D_DIM * F_DIM;
        } else {
            A0 = g_Hs + (size_t)z * T_TOK * F_DIM;
            B0 = g_w2s + (size_t)z * D_DIM * F_DIM;
        }
    }

    extern __shared__ __align__(128) char dsm[];
    __shared__ int s_tok[BM];
    uint32_t sbase = smem_u32(dsm);

    int tid = threadIdx.x, wid = tid >> 5, lane = tid & 31;

    if (LAYER == 1) {
        // gather map (identity for shared planes)
        for (int i = tid; i < BM; i += TMMA)
            s_tok[i] = routed ? g_row_token[row0 + i] : (row0 + i);
        __syncthreads();
    }

    auto load_chunk = [&](int ci) {
        uint32_t sb = sbase + (ci % STAGES) * STAGE_B;
        int kk = ci * CK;
#pragma unroll
        for (int j = 0; j < 8; j++) {
            int idx = tid + j * TMMA;           // 0..1023
            int r = idx >> 3, u = idx & 7;
            uint32_t so = r * 128 + ((u ^ (r & 7)) * 16);
            int ar = (LAYER == 1) ? s_tok[r] : (row0 + r);
            cp16(sb + so,           A0 + (size_t)ar * KA + kk + u * 8);
            cp16(sb + PLANE_B + so, B0 + (size_t)(col0 + r) * KA + kk + u * 8);
        }
        cp_commit();
    };

    // warp layout: 2x2 grid of 64x64 warp tiles
    int wr = (wid >> 1) * 64, wc = (wid & 1) * 64;
    int grp = lane >> 2, qp = lane & 3;
    int rl = lane & 15, hi = lane >> 4;

    float c[4][8][4];
#pragma unroll
    for (int i = 0; i < 4; i++)
#pragma unroll
        for (int j = 0; j < 8; j++)
#pragma unroll
            for (int q = 0; q < 4; q++) c[i][j][q] = 0.f;

    // prefetch STAGES-1 chunks
    int npre = NK < (STAGES - 1) ? NK : (STAGES - 1);
    for (int ci = 0; ci < npre; ci++) load_chunk(ci);

    uint32_t ah[2][4][4], bq[2][8][2];     // double-buffered fragments

    auto ld_frags = [&](uint32_t sb, int ks, int pb) {
        int cch = 2 * ks + hi;
#pragma unroll
        for (int mt = 0; mt < 4; mt++) {
            int r = wr + mt * 16 + rl;
            uint32_t ad = sb + r * 128 + ((cch ^ (r & 7)) << 4);
            ldsm4(ah[pb][mt][0], ah[pb][mt][1], ah[pb][mt][2], ah[pb][mt][3], ad);
        }
#pragma unroll
        for (int p = 0; p < 4; p++) {
            int r = wc + p * 16 + rl;
            uint32_t ad = sb + PLANE_B + r * 128 + ((cch ^ (r & 7)) << 4);
            uint32_t q0, q1, q2, q3;
            ldsm4(q0, q1, q2, q3, ad);
            bq[pb][2*p][0] = q0; bq[pb][2*p+1][0] = q1;
            bq[pb][2*p][1] = q2; bq[pb][2*p+1][1] = q3;
        }
    };

    for (int i = 0; i < NK; i++) {
        int issued = (NK < i + STAGES - 1) ? NK : (i + STAGES - 1);
        int pend = issued - i - 1;
        if (pend >= 1) asm volatile("cp.async.wait_group 1;" ::: "memory");
        else           asm volatile("cp.async.wait_group 0;" ::: "memory");
        __syncthreads();   // chunk i visible; slot (i-1)%S free

        if (i + STAGES - 1 < NK) load_chunk(i + STAGES - 1);

        uint32_t sb = sbase + (i % STAGES) * STAGE_B;
        ld_frags(sb, 0, 0);
#pragma unroll
        for (int ks = 0; ks < 4; ks++) {
            int cur = ks & 1;
            if (ks < 3) ld_frags(sb, ks + 1, cur ^ 1);
#pragma unroll
            for (int mt = 0; mt < 4; mt++)
#pragma unroll
                for (int nt = 0; nt < 8; nt++)
                    mma_f16(c[mt][nt][0], c[mt][nt][1], c[mt][nt][2], c[mt][nt][3],
                            ah[cur][mt][0], ah[cur][mt][1], ah[cur][mt][2], ah[cur][mt][3],
                            bq[cur][nt][0], bq[cur][nt][1]);
        }
    }

    // ---- epilogue ----
#pragma unroll
    for (int mt = 0; mt < 4; ++mt) {
        int r = row0 + wr + mt * 16 + grp;
#pragma unroll
        for (int nt = 0; nt < 8; ++nt) {
            int cg = col0 + wc + nt * 8 + qp * 2;
            float c0 = c[mt][nt][0], c1 = c[mt][nt][1];
            float c2 = c[mt][nt][2], c3 = c[mt][nt][3];
            if (LAYER == 1) {
                const float* bz = routed ? (bias_r + (size_t)e * F_DIM)
                                         : (bias_s + (size_t)z * F_DIM);
                float b0 = bz[cg], b1 = bz[cg + 1];
                float h0 = gelu_exact(c0 + b0), h1 = gelu_exact(c1 + b1);
                float h2 = gelu_exact(c2 + b0), h3 = gelu_exact(c3 + b1);
                __half* Hh = routed ? g_Hr : (g_Hs + (size_t)z * T_TOK * F_DIM);
                *(__half2*)(Hh + (size_t)r * F_DIM + cg) =
                    __halves2half2(__float2half_rn(h0), __float2half_rn(h1));
                *(__half2*)(Hh + (size_t)(r + 8) * F_DIM + cg) =
                    __halves2half2(__float2half_rn(h2), __float2half_rn(h3));
            } else {
                if (routed) {
                    const float* bz = bias_r + (size_t)e * D_DIM;
                    float b0 = bz[cg], b1 = bz[cg + 1];
                    float2 v;
                    v.x = c0 + b0; v.y = c1 + b1;
                    *(float2*)&g_Or[(size_t)r * D_DIM + cg] = v;
                    v.x = c2 + b0; v.y = c3 + b1;
                    *(float2*)&g_Or[(size_t)(r + 8) * D_DIM + cg] = v;
                } else if (z == 0) {
                    float b0 = bias_s[cg] + bias_s[D_DIM + cg];
                    float b1 = bias_s[cg + 1] + bias_s[D_DIM + cg + 1];
                    float2 v;
                    v.x = c0 + b0; v.y = c1 + b1;
                    *(float2*)&outF[(size_t)r * D_DIM + cg] = v;
                    v.x = c2 + b0; v.y = c3 + b1;
                    *(float2*)&outF[(size_t)(r + 8) * D_DIM + cg] = v;
                } else {
                    float2 v;
                    v.x = c0; v.y = c1;
                    *(float2*)&g_Os[(size_t)r * D_DIM + cg] = v;
                    v.x = c2; v.y = c3;
                    *(float2*)&g_Os[(size_t)(r + 8) * D_DIM + cg] = v;
                }
            }
        }
    }
}

// ---- combine: out += shared plane-1 partial + weighted routed ----
__global__ void k_combine(float* __restrict__ out) {
    int idx = blockIdx.x * blockDim.x + threadIdx.x;
    if (idx >= T_TOK * (D_DIM / 4)) return;
    int t = idx >> 7;
    int dq = idx & 127;
    float4 o = ((float4*)out)[t * 128 + dq];
    float4 s = ((const float4*)g_Os)[t * 128 + dq];
    int r0 = g_rows[t * 2 + 0], r1 = g_rows[t * 2 + 1];
    float w0 = g_wt[t * 2 + 0], w1 = g_wt[t * 2 + 1];
    float4 a = ((const float4*)g_Or)[(size_t)r0 * 128 + dq];
    float4 b = ((const float4*)g_Or)[(size_t)r1 * 128 + dq];
    o.x += s.x + w0 * a.x + w1 * b.x;
    o.y += s.y + w0 * a.y + w1 * b.y;
    o.z += s.z + w0 * a.z + w1 * b.z;
    o.w += s.w + w0 * a.w + w1 * b.w;
    ((float4*)out)[t * 128 + dq] = o;
}

extern "C" void kernel_launch(void* const* d_in, const int* in_sizes, int n_in,
                              void* d_out, int out_size) {
    const float* x   = (const float*)d_in[0];
    const float* gw  = (const float*)d_in[1];
    const float* gb  = (const float*)d_in[2];
    const float* sw1 = (const float*)d_in[3];
    const float* sb1 = (const float*)d_in[4];
    const float* sw2 = (const float*)d_in[5];
    const float* sb2 = (const float*)d_in[6];
    const float* rw1 = (const float*)d_in[7];
    const float* rb1 = (const float*)d_in[8];
    const float* rw2 = (const float*)d_in[9];
    const float* rb2 = (const float*)d_in[10];
    float* out = (float*)d_out;

    static int smem_set = 0;
    if (!smem_set) {
        cudaFuncSetAttribute(k_mma<1>, cudaFuncAttributeMaxDynamicSharedMemorySize, DSMEM_B);
        cudaFuncSetAttribute(k_mma<2>, cudaFuncAttributeMaxDynamicSharedMemorySize, DSMEM_B);
        smem_set = 1;
    }

    // fused conversion (all weights + x) + state reset
    k_cvt_all<<<5632, 256>>>((const float4*)x, (const float4*)sw1, (const float4*)sw2,
                             (const float4*)rw1, (const float4*)rw2);
    // router + slot assignment
    k_router<<<T_TOK / 8, 256>>>(x, gw, gb);

    dim3 blk(TMMA);
    // FFN1: shared planes + routed experts in one launch
    k_mma<1><<<dim3(F_DIM / BN, T_TOK / BM, NS_SH + E_EXP), blk, DSMEM_B>>>(sb1, rb1, nullptr);
    // FFN2: shared planes + routed experts in one launch
    k_mma<2><<<dim3(D_DIM / BN, T_TOK / BM, NS_SH + E_EXP), blk, DSMEM_B>>>(sb2, rb2, out);
    // combine
    k_combine<<<(T_TOK * (D_DIM / 4) + 255) / 256, 256>>>(out);
}